// round 8
// baseline (speedup 1.0000x reference)
#include <cuda_runtime.h>
#include <cuda_fp16.h>
#include <math.h>
#include <stdint.h>

// Problem constants
#define Bsz   4
#define Tn    4096
#define Dn    1024
#define Hn    8
#define MHn   2048
#define Mtok  (Bsz * Tn)          // 16384 tokens
#define EPSv  1e-6f

// GEMM tile config: 128(M) x 256(N) CTA tile, 8 warps with 64x64 warp tiles,
// BK=32 per stage, 4 stages, prefetch distance 3, one __syncthreads per iter.
#define BM 128
#define BN 256
#define BKh 32                     // K-halves per stage
#define NST 4                      // pipeline stages
#define ASTRIDE 40                 // smem row stride in halves -> conflict-free ldmatrix
#define STAGE_A  (BM * ASTRIDE * 2)             // 10240 B
#define STAGE_B  (BN * ASTRIDE * 2)             // 20480 B
#define STAGEB   (STAGE_A + STAGE_B)            // 30720 B
#define SMEM_MMA (NST * STAGEB)                 // 122880 B

// ---------------------------------------------------------------------------
// Device-global scratch (no cudaMalloc).  Weights: exact-integer fp16 [N,K].
// ---------------------------------------------------------------------------
__device__ __half g_wq_in[(size_t)MHn * Dn];
__device__ __half g_wq_o [(size_t)Dn  * Dn];
__device__ __half g_wq_mi[(size_t)MHn * Dn];
__device__ __half g_wq_mo[(size_t)Dn  * MHn];
__device__ float g_sc_in[MHn];
__device__ float g_sc_o [Dn];
__device__ float g_sc_mi[MHn];
__device__ float g_sc_mo[Dn];
__device__ __half g_h    [(size_t)Mtok * Dn];    // rmsnorm out (reused for h2)
__device__ float  g_qkv  [(size_t)Mtok * MHn];   // qkv fp32
__device__ __half g_gated[(size_t)Mtok * Dn];    // gated fp16
__device__ __half g_act  [(size_t)Mtok * MHn];   // gelu out fp16
__device__ float  g_x2   [(size_t)Mtok * Dn];    // post-attn residual

// ---------------------------------------------------------------------------
// PTX helpers
// ---------------------------------------------------------------------------
__device__ __forceinline__ uint32_t smem_u32(const void* p) {
    return (uint32_t)__cvta_generic_to_shared(p);
}
__device__ __forceinline__ void cpa16(uint32_t s, const void* g) {
    asm volatile("cp.async.cg.shared.global [%0], [%1], 16;" :: "r"(s), "l"(g));
}
__device__ __forceinline__ void cpa_commit() {
    asm volatile("cp.async.commit_group;");
}
__device__ __forceinline__ void ldsm4(uint32_t& r0, uint32_t& r1, uint32_t& r2, uint32_t& r3,
                                      uint32_t addr) {
    asm volatile("ldmatrix.sync.aligned.m8n8.x4.shared.b16 {%0,%1,%2,%3}, [%4];"
                 : "=r"(r0), "=r"(r1), "=r"(r2), "=r"(r3) : "r"(addr));
}
__device__ __forceinline__ void mma16816(float* c, uint32_t a0, uint32_t a1, uint32_t a2,
                                         uint32_t a3, uint32_t b0, uint32_t b1) {
    asm volatile("mma.sync.aligned.m16n8k16.row.col.f32.f16.f16.f32 "
                 "{%0,%1,%2,%3}, {%4,%5,%6,%7}, {%8,%9}, {%0,%1,%2,%3};"
                 : "+f"(c[0]), "+f"(c[1]), "+f"(c[2]), "+f"(c[3])
                 : "r"(a0), "r"(a1), "r"(a2), "r"(a3), "r"(b0), "r"(b1));
}

// ---------------------------------------------------------------------------
// Quantize: wq[n,k] = fp16(round(w/scale))  (exact integers), scales[n]=scale
// ---------------------------------------------------------------------------
__global__ void quantize_rows_kernel(const float* __restrict__ w,
                                     __half* __restrict__ wq,
                                     float* __restrict__ scales, int C) {
    int row = blockIdx.x;
    const float* wr = w + (size_t)row * C;
    float m = 0.f;
    for (int i = threadIdx.x; i < C; i += blockDim.x)
        m = fmaxf(m, fabsf(wr[i]));
    __shared__ float sh[32];
    int lane = threadIdx.x & 31, wid = threadIdx.x >> 5;
#pragma unroll
    for (int o = 16; o; o >>= 1) m = fmaxf(m, __shfl_xor_sync(0xffffffffu, m, o));
    if (lane == 0) sh[wid] = m;
    __syncthreads();
    if (wid == 0) {
        float v = (lane < (blockDim.x >> 5)) ? sh[lane] : 0.f;
#pragma unroll
        for (int o = 16; o; o >>= 1) v = fmaxf(v, __shfl_xor_sync(0xffffffffu, v, o));
        if (lane == 0) sh[0] = v;
    }
    __syncthreads();
    float scale = fmaxf(sh[0] * (1.0f / 127.0f), 1e-8f);
    if (threadIdx.x == 0) scales[row] = scale;
    for (int i = threadIdx.x; i < C; i += blockDim.x)
        wq[(size_t)row * C + i] = __float2half_rn(rintf(wr[i] / scale));
}

// ---------------------------------------------------------------------------
// RMSNorm -> fp16
// ---------------------------------------------------------------------------
__global__ void rmsnorm_kernel(const float* __restrict__ x,
                               const float* __restrict__ w,
                               __half* __restrict__ out) {
    int row = blockIdx.x;
    const float* xr = x + (size_t)row * Dn;
    float ss = 0.f;
    for (int i = threadIdx.x; i < Dn; i += blockDim.x) {
        float v = xr[i];
        ss += v * v;
    }
    __shared__ float sh[32];
    int lane = threadIdx.x & 31, wid = threadIdx.x >> 5;
#pragma unroll
    for (int o = 16; o; o >>= 1) ss += __shfl_xor_sync(0xffffffffu, ss, o);
    if (lane == 0) sh[wid] = ss;
    __syncthreads();
    if (wid == 0) {
        float v = (lane < (blockDim.x >> 5)) ? sh[lane] : 0.f;
#pragma unroll
        for (int o = 16; o; o >>= 1) v += __shfl_xor_sync(0xffffffffu, v, o);
        if (lane == 0) sh[0] = v;
    }
    __syncthreads();
    float inv = rsqrtf(sh[0] * (1.0f / Dn) + EPSv);
    for (int i = threadIdx.x; i < Dn; i += blockDim.x)
        out[(size_t)row * Dn + i] = __float2half_rn(xr[i] * inv * w[i]);
}

// ---------------------------------------------------------------------------
// Causal exp-filter conv (linear recurrence, chunked w/ 512-step warmup) + SiLU
// ---------------------------------------------------------------------------
#define SCH 512
__global__ void scan_gate_kernel(const float* __restrict__ qkv,
                                 const float* __restrict__ filt,
                                 __half* __restrict__ gated) {
    int tid = threadIdx.x;
    int chunk = blockIdx.x & 7;
    int b = (blockIdx.x >> 3) & 3;
    int cg = blockIdx.x >> 5;
    int c = cg * 256 + tid;
    int h = c >> 7;
    float f0 = filt[h];
    float alpha = filt[Hn + h] / f0;
    const float* base = qkv + (size_t)b * Tn * MHn;
    __half* ob = gated + (size_t)b * Tn * Dn;
    float y = 0.f;
    int t0 = chunk * SCH;
    if (chunk) {
#pragma unroll 4
        for (int t = t0 - SCH; t < t0; ++t)
            y = fmaf(alpha, y, base[(size_t)t * MHn + c]);
    }
#pragma unroll 2
    for (int t = t0; t < t0 + SCH; ++t) {
        float s = base[(size_t)t * MHn + c];
        float g = base[(size_t)t * MHn + Dn + c];
        y = fmaf(alpha, y, s);
        float sig = 1.0f / (1.0f + expf(-g));
        ob[(size_t)t * Dn + c] = __float2half_rn((f0 * y) * (g * sig));
    }
}

// ---------------------------------------------------------------------------
// fp16 tensor-core GEMM: v[m,n] = (sum_k A[m,k]*W[n,k]) * scales[n]
//   EPI 0: Cf = v     EPI 1: Cf = v + Add     EPI 2: Ch = fp16(gelu(v))
// 128x256 tile, 8 warps (2m x 4n), 64x64 warp tile, BK=32, NST=4, prefetch 3,
// wait_group 2 steady-state, ONE __syncthreads per iteration.
// ---------------------------------------------------------------------------
template <int EPI>
__global__ __launch_bounds__(256)
void mma_gemm(const __half* __restrict__ A, const __half* __restrict__ W,
              const float* __restrict__ scales, const float* __restrict__ Add,
              float* __restrict__ Cf, __half* __restrict__ Ch,
              int M, int N, int K) {
    extern __shared__ char smem[];
    uint32_t s0 = smem_u32(smem);

    int tid = threadIdx.x;
    int bm = blockIdx.y * BM;
    int bn = blockIdx.x * BN;
    int lane = tid & 31, wid = tid >> 5;
    int wm = wid & 1;            // 2 m-groups of 64 rows
    int wn = wid >> 1;           // 4 n-groups of 64 cols

    // loader: A 128 rows x 64B = 512 chunks (2/thread); B 256 rows x 64B (4/thread)
    int lr = tid >> 2;           // 0..63
    int lc = tid & 3;            // 16B chunk in row

    const __half* Ab = A + (size_t)(bm + lr) * K + lc * 8;
    const __half* Bb = W + (size_t)(bn + lr) * K + lc * 8;
    uint32_t soff = (uint32_t)(lr * ASTRIDE + lc * 8) * 2;
    const uint32_t row64 = 64 * ASTRIDE * 2;

    auto load_tile = [&](int kt) {
        uint32_t tb = s0 + (kt & (NST - 1)) * STAGEB;
        const __half* ag = Ab + (size_t)kt * BKh;
        const __half* bg = Bb + (size_t)kt * BKh;
        cpa16(tb + soff, ag);
        cpa16(tb + soff + row64, ag + (size_t)64 * K);
        uint32_t bbse = tb + STAGE_A + soff;
        cpa16(bbse, bg);
        cpa16(bbse + row64, bg + (size_t)64 * K);
        cpa16(bbse + 2 * row64, bg + (size_t)128 * K);
        cpa16(bbse + 3 * row64, bg + (size_t)192 * K);
        cpa_commit();
    };

    float c[4][8][4];
#pragma unroll
    for (int i = 0; i < 4; ++i)
#pragma unroll
        for (int j = 0; j < 8; ++j)
#pragma unroll
            for (int l = 0; l < 4; ++l) c[i][j][l] = 0.f;

    int KT = K / BKh;
    load_tile(0);
    load_tile(1);
    load_tile(2);

    for (int kt = 0; kt < KT; ++kt) {
        if (kt < KT - 2)       asm volatile("cp.async.wait_group 2;");
        else if (kt == KT - 2) asm volatile("cp.async.wait_group 1;");
        else                   asm volatile("cp.async.wait_group 0;");
        __syncthreads();                    // warps done with kt-1; tile kt visible

        if (kt + 3 < KT) load_tile(kt + 3); // overwrites buffer of kt-1: safe

        uint32_t aBase = s0 + (kt & (NST - 1)) * STAGEB;
        uint32_t bBase = aBase + STAGE_A;
#pragma unroll
        for (int ks = 0; ks < 2; ++ks) {
            uint32_t a[4][4];
#pragma unroll
            for (int mt = 0; mt < 4; ++mt) {
                int row = wm * 64 + mt * 16 + (lane & 15);
                int col = ks * 16 + (lane >> 4) * 8;
                ldsm4(a[mt][0], a[mt][1], a[mt][2], a[mt][3],
                      aBase + (row * ASTRIDE + col) * 2);
            }
            uint32_t b[4][4];
#pragma unroll
            for (int p = 0; p < 4; ++p) {
                int nrow = wn * 64 + p * 16 + (lane & 7) + ((lane >> 4) << 3);
                int col = ks * 16 + ((lane >> 3) & 1) * 8;
                ldsm4(b[p][0], b[p][1], b[p][2], b[p][3],
                      bBase + (nrow * ASTRIDE + col) * 2);
            }
#pragma unroll
            for (int mt = 0; mt < 4; ++mt)
#pragma unroll
                for (int nt = 0; nt < 8; ++nt)
                    mma16816(c[mt][nt], a[mt][0], a[mt][1], a[mt][2], a[mt][3],
                             b[nt >> 1][(nt & 1) * 2], b[nt >> 1][(nt & 1) * 2 + 1]);
        }
    }

    // Epilogue
#pragma unroll
    for (int mt = 0; mt < 4; ++mt) {
#pragma unroll
        for (int nt = 0; nt < 8; ++nt) {
            int r0 = bm + wm * 64 + mt * 16 + (lane >> 2);
            int col = bn + wn * 64 + nt * 8 + (lane & 3) * 2;
            float sc0 = __ldg(&scales[col]);
            float sc1 = __ldg(&scales[col + 1]);
#pragma unroll
            for (int half = 0; half < 2; ++half) {
                int row = r0 + half * 8;
                float v0 = c[mt][nt][half * 2 + 0] * sc0;
                float v1 = c[mt][nt][half * 2 + 1] * sc1;
                if (EPI == 0) {
                    float2 o = {v0, v1};
                    *(float2*)&Cf[(size_t)row * N + col] = o;
                } else if (EPI == 1) {
                    float2 r = *(const float2*)&Add[(size_t)row * N + col];
                    float2 o = {v0 + r.x, v1 + r.y};
                    *(float2*)&Cf[(size_t)row * N + col] = o;
                } else {
                    float g0 = 0.5f * v0 * (1.0f + erff(v0 * 0.70710678118654752440f));
                    float g1 = 0.5f * v1 * (1.0f + erff(v1 * 0.70710678118654752440f));
                    __half2 o = {__float2half_rn(g0), __float2half_rn(g1)};
                    *(__half2*)&Ch[(size_t)row * N + col] = o;
                }
            }
        }
    }
}

// ---------------------------------------------------------------------------
// Launch
// ---------------------------------------------------------------------------
extern "C" void kernel_launch(void* const* d_in, const int* in_sizes, int n_in,
                              void* d_out, int out_size) {
    (void)in_sizes; (void)n_in; (void)out_size;
    const float* x    = (const float*)d_in[0];
    const float* n1w  = (const float*)d_in[1];
    const float* n2w  = (const float*)d_in[2];
    const float* w_in = (const float*)d_in[3];
    const float* w_o  = (const float*)d_in[4];
    const float* w_mi = (const float*)d_in[5];
    const float* w_mo = (const float*)d_in[6];
    const float* filt = (const float*)d_in[7];
    float* out = (float*)d_out;

    __half *p_wq_in, *p_wq_o, *p_wq_mi, *p_wq_mo, *p_h, *p_gated, *p_act;
    float *p_sc_in, *p_sc_o, *p_sc_mi, *p_sc_mo, *p_qkv, *p_x2;
    cudaGetSymbolAddress((void**)&p_wq_in, g_wq_in);
    cudaGetSymbolAddress((void**)&p_wq_o,  g_wq_o);
    cudaGetSymbolAddress((void**)&p_wq_mi, g_wq_mi);
    cudaGetSymbolAddress((void**)&p_wq_mo, g_wq_mo);
    cudaGetSymbolAddress((void**)&p_sc_in, g_sc_in);
    cudaGetSymbolAddress((void**)&p_sc_o,  g_sc_o);
    cudaGetSymbolAddress((void**)&p_sc_mi, g_sc_mi);
    cudaGetSymbolAddress((void**)&p_sc_mo, g_sc_mo);
    cudaGetSymbolAddress((void**)&p_h,     g_h);
    cudaGetSymbolAddress((void**)&p_qkv,   g_qkv);
    cudaGetSymbolAddress((void**)&p_gated, g_gated);
    cudaGetSymbolAddress((void**)&p_act,   g_act);
    cudaGetSymbolAddress((void**)&p_x2,    g_x2);

    cudaFuncSetAttribute(mma_gemm<0>, cudaFuncAttributeMaxDynamicSharedMemorySize, SMEM_MMA);
    cudaFuncSetAttribute(mma_gemm<1>, cudaFuncAttributeMaxDynamicSharedMemorySize, SMEM_MMA);
    cudaFuncSetAttribute(mma_gemm<2>, cudaFuncAttributeMaxDynamicSharedMemorySize, SMEM_MMA);

    // 1) quantize weights -> exact fp16 integers + scales
    quantize_rows_kernel<<<MHn, 256>>>(w_in, p_wq_in, p_sc_in, Dn);
    quantize_rows_kernel<<<Dn,  256>>>(w_o,  p_wq_o,  p_sc_o,  Dn);
    quantize_rows_kernel<<<MHn, 256>>>(w_mi, p_wq_mi, p_sc_mi, Dn);
    quantize_rows_kernel<<<Dn,  256>>>(w_mo, p_wq_mo, p_sc_mo, MHn);

    // 2) h = rmsnorm(x) -> fp16
    rmsnorm_kernel<<<Mtok, 256>>>(x, n1w, p_h);

    // 3) qkv = h @ Wq_in^T (fp32 out)
    mma_gemm<0><<<dim3(MHn / BN, Mtok / BM), 256, SMEM_MMA>>>(
        p_h, p_wq_in, p_sc_in, nullptr, p_qkv, nullptr, Mtok, MHn, Dn);

    // 4) causal conv recurrence + SiLU gate -> fp16
    scan_gate_kernel<<<128, 256>>>(p_qkv, filt, p_gated);

    // 5) x2 = x + gated @ Wq_o^T
    mma_gemm<1><<<dim3(Dn / BN, Mtok / BM), 256, SMEM_MMA>>>(
        p_gated, p_wq_o, p_sc_o, x, p_x2, nullptr, Mtok, Dn, Dn);

    // 6) h2 = rmsnorm(x2) -> fp16
    rmsnorm_kernel<<<Mtok, 256>>>(p_x2, n2w, p_h);

    // 7) m = gelu(h2 @ Wq_mi^T) -> fp16
    mma_gemm<2><<<dim3(MHn / BN, Mtok / BM), 256, SMEM_MMA>>>(
        p_h, p_wq_mi, p_sc_mi, nullptr, nullptr, p_act, Mtok, MHn, Dn);

    // 8) out = x2 + m @ Wq_mo^T
    mma_gemm<1><<<dim3(Dn / BN, Mtok / BM), 256, SMEM_MMA>>>(
        p_act, p_wq_mo, p_sc_mo, p_x2, out, nullptr, Mtok, Dn, MHn);
}

// round 9
// speedup vs baseline: 1.2127x; 1.2127x over previous
#include <cuda_runtime.h>
#include <cuda_fp16.h>
#include <math.h>
#include <stdint.h>

// Problem constants
#define Bsz   4
#define Tn    4096
#define Dn    1024
#define Hn    8
#define MHn   2048
#define Mtok  (Bsz * Tn)          // 16384 tokens
#define EPSv  1e-6f

// GEMM tile config (round-4 proven best): 128x128 CTA tile, BK=32/stage,
// NST=4, prefetch distance 3, wait_group 2, 2 CTAs/SM, ONE sync per iter.
#define BM 128
#define BN 128
#define BKh 32                     // K-halves per stage
#define NST 4                      // pipeline stages
#define ASTRIDE 40                 // smem row stride in halves -> conflict-free ldmatrix
#define STAGE_A  (BM * ASTRIDE * 2)             // 10240 B
#define STAGE_B  (BN * ASTRIDE * 2)             // 10240 B
#define STAGEB   (STAGE_A + STAGE_B)            // 20480 B
#define SMEM_MMA (NST * STAGEB)                 // 81920 B

// ---------------------------------------------------------------------------
// Device-global scratch (no cudaMalloc).  Weights: exact-integer fp16 [N,K].
// g_act doubles as the qkv buffer (qkv dead after scan; act written after).
// ---------------------------------------------------------------------------
__device__ __half g_wq_in[(size_t)MHn * Dn];
__device__ __half g_wq_o [(size_t)Dn  * Dn];
__device__ __half g_wq_mi[(size_t)MHn * Dn];
__device__ __half g_wq_mo[(size_t)Dn  * MHn];
__device__ float g_sc_in[MHn];
__device__ float g_sc_o [Dn];
__device__ float g_sc_mi[MHn];
__device__ float g_sc_mo[Dn];
__device__ __half g_h    [(size_t)Mtok * Dn];    // rmsnorm out (reused for h2)
__device__ __half g_gated[(size_t)Mtok * Dn];    // gated fp16
__device__ __half g_act  [(size_t)Mtok * MHn];   // qkv fp16, then gelu out fp16
__device__ float  g_x2   [(size_t)Mtok * Dn];    // post-attn residual

// ---------------------------------------------------------------------------
// PTX helpers
// ---------------------------------------------------------------------------
__device__ __forceinline__ uint32_t smem_u32(const void* p) {
    return (uint32_t)__cvta_generic_to_shared(p);
}
__device__ __forceinline__ void cpa16(uint32_t s, const void* g) {
    asm volatile("cp.async.cg.shared.global [%0], [%1], 16;" :: "r"(s), "l"(g));
}
__device__ __forceinline__ void cpa_commit() {
    asm volatile("cp.async.commit_group;");
}
__device__ __forceinline__ void ldsm4(uint32_t& r0, uint32_t& r1, uint32_t& r2, uint32_t& r3,
                                      uint32_t addr) {
    asm volatile("ldmatrix.sync.aligned.m8n8.x4.shared.b16 {%0,%1,%2,%3}, [%4];"
                 : "=r"(r0), "=r"(r1), "=r"(r2), "=r"(r3) : "r"(addr));
}
__device__ __forceinline__ void mma16816(float* c, uint32_t a0, uint32_t a1, uint32_t a2,
                                         uint32_t a3, uint32_t b0, uint32_t b1) {
    asm volatile("mma.sync.aligned.m16n8k16.row.col.f32.f16.f16.f32 "
                 "{%0,%1,%2,%3}, {%4,%5,%6,%7}, {%8,%9}, {%0,%1,%2,%3};"
                 : "+f"(c[0]), "+f"(c[1]), "+f"(c[2]), "+f"(c[3])
                 : "r"(a0), "r"(a1), "r"(a2), "r"(a3), "r"(b0), "r"(b1));
}

// ---------------------------------------------------------------------------
// Quantize: wq[n,k] = fp16(round(w/scale))  (exact integers), scales[n]=scale
// ---------------------------------------------------------------------------
__global__ void quantize_rows_kernel(const float* __restrict__ w,
                                     __half* __restrict__ wq,
                                     float* __restrict__ scales, int C) {
    int row = blockIdx.x;
    const float* wr = w + (size_t)row * C;
    float m = 0.f;
    for (int i = threadIdx.x; i < C; i += blockDim.x)
        m = fmaxf(m, fabsf(wr[i]));
    __shared__ float sh[32];
    int lane = threadIdx.x & 31, wid = threadIdx.x >> 5;
#pragma unroll
    for (int o = 16; o; o >>= 1) m = fmaxf(m, __shfl_xor_sync(0xffffffffu, m, o));
    if (lane == 0) sh[wid] = m;
    __syncthreads();
    if (wid == 0) {
        float v = (lane < (blockDim.x >> 5)) ? sh[lane] : 0.f;
#pragma unroll
        for (int o = 16; o; o >>= 1) v = fmaxf(v, __shfl_xor_sync(0xffffffffu, v, o));
        if (lane == 0) sh[0] = v;
    }
    __syncthreads();
    float scale = fmaxf(sh[0] * (1.0f / 127.0f), 1e-8f);
    if (threadIdx.x == 0) scales[row] = scale;
    for (int i = threadIdx.x; i < C; i += blockDim.x)
        wq[(size_t)row * C + i] = __float2half_rn(rintf(wr[i] / scale));
}

// ---------------------------------------------------------------------------
// RMSNorm -> fp16, vectorized (float4 in, 2x half2 out). 256 thr, 1 row/block.
// ---------------------------------------------------------------------------
__global__ void rmsnorm_kernel(const float* __restrict__ x,
                               const float* __restrict__ w,
                               __half* __restrict__ out) {
    int row = blockIdx.x;
    const float4* xr = (const float4*)(x + (size_t)row * Dn);
    float4 v4 = xr[threadIdx.x];                  // 256 thr x 4 = 1024
    float ss = v4.x * v4.x + v4.y * v4.y + v4.z * v4.z + v4.w * v4.w;
    __shared__ float sh[32];
    int lane = threadIdx.x & 31, wid = threadIdx.x >> 5;
#pragma unroll
    for (int o = 16; o; o >>= 1) ss += __shfl_xor_sync(0xffffffffu, ss, o);
    if (lane == 0) sh[wid] = ss;
    __syncthreads();
    if (wid == 0) {
        float v = (lane < 8) ? sh[lane] : 0.f;
#pragma unroll
        for (int o = 4; o; o >>= 1) v += __shfl_xor_sync(0xffffffffu, v, o);
        if (lane == 0) sh[0] = v;
    }
    __syncthreads();
    float inv = rsqrtf(sh[0] * (1.0f / Dn) + EPSv);
    float4 w4 = ((const float4*)w)[threadIdx.x];
    __half2 o0 = {__float2half_rn(v4.x * inv * w4.x), __float2half_rn(v4.y * inv * w4.y)};
    __half2 o1 = {__float2half_rn(v4.z * inv * w4.z), __float2half_rn(v4.w * inv * w4.w)};
    uint2 o;
    o.x = *(uint32_t*)&o0;
    o.y = *(uint32_t*)&o1;
    *(uint2*)&out[(size_t)row * Dn + threadIdx.x * 4] = o;
}

// ---------------------------------------------------------------------------
// Causal exp-filter conv (linear recurrence, chunked w/ 512-step warmup) + SiLU
// qkv now fp16.
// ---------------------------------------------------------------------------
#define SCH 512
__global__ void scan_gate_kernel(const __half* __restrict__ qkv,
                                 const float* __restrict__ filt,
                                 __half* __restrict__ gated) {
    int tid = threadIdx.x;
    int chunk = blockIdx.x & 7;
    int b = (blockIdx.x >> 3) & 3;
    int cg = blockIdx.x >> 5;
    int c = cg * 256 + tid;
    int h = c >> 7;
    float f0 = filt[h];
    float alpha = filt[Hn + h] / f0;
    const __half* base = qkv + (size_t)b * Tn * MHn;
    __half* ob = gated + (size_t)b * Tn * Dn;
    float y = 0.f;
    int t0 = chunk * SCH;
    if (chunk) {
#pragma unroll 4
        for (int t = t0 - SCH; t < t0; ++t)
            y = fmaf(alpha, y, __half2float(__ldg(&base[(size_t)t * MHn + c])));
    }
#pragma unroll 2
    for (int t = t0; t < t0 + SCH; ++t) {
        float s = __half2float(__ldg(&base[(size_t)t * MHn + c]));
        float g = __half2float(__ldg(&base[(size_t)t * MHn + Dn + c]));
        y = fmaf(alpha, y, s);
        float sig = 1.0f / (1.0f + expf(-g));
        ob[(size_t)t * Dn + c] = __float2half_rn((f0 * y) * (g * sig));
    }
}

// ---------------------------------------------------------------------------
// fp16 tensor-core GEMM: v[m,n] = (sum_k A[m,k]*W[n,k]) * scales[n]
//   EPI 1: Cf = v + Add (fp32)   EPI 2: Ch = fp16(gelu(v))   EPI 3: Ch = fp16(v)
// 128x128 tile, 8 warps (4m x 2n, 32x64 warp tile), BK=32, NST=4, prefetch 3,
// wait_group 2, ONE __syncthreads per iteration, 2 CTAs/SM.
// ---------------------------------------------------------------------------
template <int EPI>
__global__ __launch_bounds__(256, 2)
void mma_gemm(const __half* __restrict__ A, const __half* __restrict__ W,
              const float* __restrict__ scales, const float* __restrict__ Add,
              float* __restrict__ Cf, __half* __restrict__ Ch,
              int M, int N, int K) {
    extern __shared__ char smem[];
    uint32_t s0 = smem_u32(smem);

    int tid = threadIdx.x;
    int bm = blockIdx.y * BM;
    int bn = blockIdx.x * BN;
    int lane = tid & 31, wid = tid >> 5;
    int wm = wid >> 1, wn = wid & 1;

    int lr = tid >> 2;          // 0..63 load row
    int lc = tid & 3;           // 16B chunk within 64B row

    const __half* Ab = A + (size_t)(bm + lr) * K + lc * 8;
    const __half* Bb = W + (size_t)(bn + lr) * K + lc * 8;
    uint32_t aoff = (uint32_t)(lr * ASTRIDE + lc * 8) * 2;
    const uint32_t rowOfs64 = 64 * ASTRIDE * 2;

    auto load_tile = [&](int kt) {
        uint32_t tb = s0 + (kt & (NST - 1)) * STAGEB;
        const __half* ag = Ab + (size_t)kt * BKh;
        const __half* bg = Bb + (size_t)kt * BKh;
        cpa16(tb + aoff, ag);
        cpa16(tb + aoff + rowOfs64, ag + (size_t)64 * K);
        cpa16(tb + STAGE_A + aoff, bg);
        cpa16(tb + STAGE_A + aoff + rowOfs64, bg + (size_t)64 * K);
        cpa_commit();
    };

    float c[2][8][4];
#pragma unroll
    for (int i = 0; i < 2; ++i)
#pragma unroll
        for (int j = 0; j < 8; ++j)
#pragma unroll
            for (int l = 0; l < 4; ++l) c[i][j][l] = 0.f;

    int KT = K / BKh;
    load_tile(0);
    load_tile(1);
    load_tile(2);

    for (int kt = 0; kt < KT; ++kt) {
        if (kt < KT - 2)       asm volatile("cp.async.wait_group 2;");
        else if (kt == KT - 2) asm volatile("cp.async.wait_group 1;");
        else                   asm volatile("cp.async.wait_group 0;");
        __syncthreads();                    // warps done with kt-1; tile kt visible

        if (kt + 3 < KT) load_tile(kt + 3); // overwrites buffer of kt-1: safe

        uint32_t aBase = s0 + (kt & (NST - 1)) * STAGEB;
        uint32_t bBase = aBase + STAGE_A;
#pragma unroll
        for (int ks = 0; ks < 2; ++ks) {
            uint32_t a[2][4];
#pragma unroll
            for (int mt = 0; mt < 2; ++mt) {
                int row = wm * 32 + mt * 16 + (lane & 15);
                int col = ks * 16 + (lane >> 4) * 8;
                ldsm4(a[mt][0], a[mt][1], a[mt][2], a[mt][3],
                      aBase + (row * ASTRIDE + col) * 2);
            }
            uint32_t b[4][4];
#pragma unroll
            for (int p = 0; p < 4; ++p) {
                int nrow = wn * 64 + p * 16 + (lane & 7) + ((lane >> 4) << 3);
                int col = ks * 16 + ((lane >> 3) & 1) * 8;
                ldsm4(b[p][0], b[p][1], b[p][2], b[p][3],
                      bBase + (nrow * ASTRIDE + col) * 2);
            }
#pragma unroll
            for (int mt = 0; mt < 2; ++mt)
#pragma unroll
                for (int nt = 0; nt < 8; ++nt)
                    mma16816(c[mt][nt], a[mt][0], a[mt][1], a[mt][2], a[mt][3],
                             b[nt >> 1][(nt & 1) * 2], b[nt >> 1][(nt & 1) * 2 + 1]);
        }
    }

    // Epilogue
#pragma unroll
    for (int mt = 0; mt < 2; ++mt) {
#pragma unroll
        for (int nt = 0; nt < 8; ++nt) {
            int r0 = bm + wm * 32 + mt * 16 + (lane >> 2);
            int col = bn + wn * 64 + nt * 8 + (lane & 3) * 2;
            float sc0 = __ldg(&scales[col]);
            float sc1 = __ldg(&scales[col + 1]);
#pragma unroll
            for (int half = 0; half < 2; ++half) {
                int row = r0 + half * 8;
                float v0 = c[mt][nt][half * 2 + 0] * sc0;
                float v1 = c[mt][nt][half * 2 + 1] * sc1;
                if (EPI == 1) {
                    float2 r = *(const float2*)&Add[(size_t)row * N + col];
                    float2 o = {v0 + r.x, v1 + r.y};
                    *(float2*)&Cf[(size_t)row * N + col] = o;
                } else if (EPI == 2) {
                    float g0 = 0.5f * v0 * (1.0f + erff(v0 * 0.70710678118654752440f));
                    float g1 = 0.5f * v1 * (1.0f + erff(v1 * 0.70710678118654752440f));
                    __half2 o = {__float2half_rn(g0), __float2half_rn(g1)};
                    *(__half2*)&Ch[(size_t)row * N + col] = o;
                } else {
                    __half2 o = {__float2half_rn(v0), __float2half_rn(v1)};
                    *(__half2*)&Ch[(size_t)row * N + col] = o;
                }
            }
        }
    }
}

// ---------------------------------------------------------------------------
// Launch
// ---------------------------------------------------------------------------
extern "C" void kernel_launch(void* const* d_in, const int* in_sizes, int n_in,
                              void* d_out, int out_size) {
    (void)in_sizes; (void)n_in; (void)out_size;
    const float* x    = (const float*)d_in[0];
    const float* n1w  = (const float*)d_in[1];
    const float* n2w  = (const float*)d_in[2];
    const float* w_in = (const float*)d_in[3];
    const float* w_o  = (const float*)d_in[4];
    const float* w_mi = (const float*)d_in[5];
    const float* w_mo = (const float*)d_in[6];
    const float* filt = (const float*)d_in[7];
    float* out = (float*)d_out;

    __half *p_wq_in, *p_wq_o, *p_wq_mi, *p_wq_mo, *p_h, *p_gated, *p_act;
    float *p_sc_in, *p_sc_o, *p_sc_mi, *p_sc_mo, *p_x2;
    cudaGetSymbolAddress((void**)&p_wq_in, g_wq_in);
    cudaGetSymbolAddress((void**)&p_wq_o,  g_wq_o);
    cudaGetSymbolAddress((void**)&p_wq_mi, g_wq_mi);
    cudaGetSymbolAddress((void**)&p_wq_mo, g_wq_mo);
    cudaGetSymbolAddress((void**)&p_sc_in, g_sc_in);
    cudaGetSymbolAddress((void**)&p_sc_o,  g_sc_o);
    cudaGetSymbolAddress((void**)&p_sc_mi, g_sc_mi);
    cudaGetSymbolAddress((void**)&p_sc_mo, g_sc_mo);
    cudaGetSymbolAddress((void**)&p_h,     g_h);
    cudaGetSymbolAddress((void**)&p_gated, g_gated);
    cudaGetSymbolAddress((void**)&p_act,   g_act);
    cudaGetSymbolAddress((void**)&p_x2,    g_x2);

    cudaFuncSetAttribute(mma_gemm<1>, cudaFuncAttributeMaxDynamicSharedMemorySize, SMEM_MMA);
    cudaFuncSetAttribute(mma_gemm<2>, cudaFuncAttributeMaxDynamicSharedMemorySize, SMEM_MMA);
    cudaFuncSetAttribute(mma_gemm<3>, cudaFuncAttributeMaxDynamicSharedMemorySize, SMEM_MMA);

    // 1) quantize weights -> exact fp16 integers + scales
    quantize_rows_kernel<<<MHn, 256>>>(w_in, p_wq_in, p_sc_in, Dn);
    quantize_rows_kernel<<<Dn,  256>>>(w_o,  p_wq_o,  p_sc_o,  Dn);
    quantize_rows_kernel<<<MHn, 256>>>(w_mi, p_wq_mi, p_sc_mi, Dn);
    quantize_rows_kernel<<<Dn,  256>>>(w_mo, p_wq_mo, p_sc_mo, MHn);

    // 2) h = rmsnorm(x) -> fp16
    rmsnorm_kernel<<<Mtok, 256>>>(x, n1w, p_h);

    // 3) qkv = h @ Wq_in^T -> fp16 (stored in g_act, dead after scan)
    mma_gemm<3><<<dim3(MHn / BN, Mtok / BM), 256, SMEM_MMA>>>(
        p_h, p_wq_in, p_sc_in, nullptr, nullptr, p_act, Mtok, MHn, Dn);

    // 4) causal conv recurrence + SiLU gate -> fp16
    scan_gate_kernel<<<128, 256>>>(p_act, filt, p_gated);

    // 5) x2 = x + gated @ Wq_o^T (fp32)
    mma_gemm<1><<<dim3(Dn / BN, Mtok / BM), 256, SMEM_MMA>>>(
        p_gated, p_wq_o, p_sc_o, x, p_x2, nullptr, Mtok, Dn, Dn);

    // 6) h2 = rmsnorm(x2) -> fp16
    rmsnorm_kernel<<<Mtok, 256>>>(p_x2, n2w, p_h);

    // 7) m = gelu(h2 @ Wq_mi^T) -> fp16 (overwrites g_act)
    mma_gemm<2><<<dim3(MHn / BN, Mtok / BM), 256, SMEM_MMA>>>(
        p_h, p_wq_mi, p_sc_mi, nullptr, nullptr, p_act, Mtok, MHn, Dn);

    // 8) out = x2 + m @ Wq_mo^T (fp32)
    mma_gemm<1><<<dim3(Dn / BN, Mtok / BM), 256, SMEM_MMA>>>(
        p_act, p_wq_mo, p_sc_mo, p_x2, out, nullptr, Mtok, Dn, MHn);
}

// round 10
// speedup vs baseline: 1.4209x; 1.1717x over previous
#include <cuda_runtime.h>
#include <cuda_fp16.h>
#include <math.h>
#include <stdint.h>

// Problem constants
#define Bsz   4
#define Tn    4096
#define Dn    1024
#define Hn    8
#define MHn   2048
#define Mtok  (Bsz * Tn)          // 16384 tokens
#define EPSv  1e-6f

// GEMM tile config (proven): 128(M) x BNT(N) CTA tile, BK=32/stage, NST=4,
// prefetch distance 3, wait_group 2, 2 CTAs/SM, ONE sync per iteration.
#define BM 128
#define BKh 32                     // K-halves per stage
#define NST 4                      // pipeline stages
#define ASTRIDE 40                 // smem row stride in halves -> conflict-free ldmatrix
#define STAGE_A  (BM * ASTRIDE * 2)             // 10240 B

// ---------------------------------------------------------------------------
// Device-global scratch (no cudaMalloc).  Weights: exact-integer fp16 [N,K].
// g_act doubles as the qkv buffer (qkv dead after scan; act written after).
// ---------------------------------------------------------------------------
__device__ __half g_wq_in[(size_t)MHn * Dn];
__device__ __half g_wq_o [(size_t)Dn  * Dn];
__device__ __half g_wq_mi[(size_t)MHn * Dn];
__device__ __half g_wq_mo[(size_t)Dn  * MHn];
__device__ float g_sc_in[MHn];
__device__ float g_sc_o [Dn];
__device__ float g_sc_mi[MHn];
__device__ float g_sc_mo[Dn];
__device__ __half g_h    [(size_t)Mtok * Dn];    // rmsnorm out (reused for h2)
__device__ __half g_gated[(size_t)Mtok * Dn];    // gated fp16
__device__ __half g_act  [(size_t)Mtok * MHn];   // qkv fp16, then gelu out fp16
__device__ float  g_x2   [(size_t)Mtok * Dn];    // post-attn residual

// ---------------------------------------------------------------------------
// PTX helpers
// ---------------------------------------------------------------------------
__device__ __forceinline__ uint32_t smem_u32(const void* p) {
    return (uint32_t)__cvta_generic_to_shared(p);
}
__device__ __forceinline__ void cpa16(uint32_t s, const void* g) {
    asm volatile("cp.async.cg.shared.global [%0], [%1], 16;" :: "r"(s), "l"(g));
}
__device__ __forceinline__ void cpa_commit() {
    asm volatile("cp.async.commit_group;");
}
__device__ __forceinline__ void ldsm4(uint32_t& r0, uint32_t& r1, uint32_t& r2, uint32_t& r3,
                                      uint32_t addr) {
    asm volatile("ldmatrix.sync.aligned.m8n8.x4.shared.b16 {%0,%1,%2,%3}, [%4];"
                 : "=r"(r0), "=r"(r1), "=r"(r2), "=r"(r3) : "r"(addr));
}
__device__ __forceinline__ void mma16816(float* c, uint32_t a0, uint32_t a1, uint32_t a2,
                                         uint32_t a3, uint32_t b0, uint32_t b1) {
    asm volatile("mma.sync.aligned.m16n8k16.row.col.f32.f16.f16.f32 "
                 "{%0,%1,%2,%3}, {%4,%5,%6,%7}, {%8,%9}, {%0,%1,%2,%3};"
                 : "+f"(c[0]), "+f"(c[1]), "+f"(c[2]), "+f"(c[3])
                 : "r"(a0), "r"(a1), "r"(a2), "r"(a3), "r"(b0), "r"(b1));
}

// ---------------------------------------------------------------------------
// Quantize (register-resident single pass):
// wq[n,k] = fp16(round(w/scale)) exact integers; scales[n] = scale.
// C/4 float4 per row, 256 threads -> NV = C/1024 float4 per thread.
// ---------------------------------------------------------------------------
__global__ void quantize_rows_kernel(const float* __restrict__ w,
                                     __half* __restrict__ wq,
                                     float* __restrict__ scales, int C) {
    int row = blockIdx.x;
    int nv = C >> 10;                       // 1 (C=1024) or 2 (C=2048)
    const float4* wr = (const float4*)(w + (size_t)row * C);
    float4 v[2];
    float m = 0.f;
    for (int j = 0; j < nv; ++j) {
        v[j] = wr[j * 256 + threadIdx.x];
        m = fmaxf(m, fmaxf(fmaxf(fabsf(v[j].x), fabsf(v[j].y)),
                           fmaxf(fabsf(v[j].z), fabsf(v[j].w))));
    }
    __shared__ float sh[32];
    int lane = threadIdx.x & 31, wid = threadIdx.x >> 5;
#pragma unroll
    for (int o = 16; o; o >>= 1) m = fmaxf(m, __shfl_xor_sync(0xffffffffu, m, o));
    if (lane == 0) sh[wid] = m;
    __syncthreads();
    if (wid == 0) {
        float t = (lane < 8) ? sh[lane] : 0.f;
#pragma unroll
        for (int o = 4; o; o >>= 1) t = fmaxf(t, __shfl_xor_sync(0xffffffffu, t, o));
        if (lane == 0) sh[0] = t;
    }
    __syncthreads();
    float scale = fmaxf(sh[0] * (1.0f / 127.0f), 1e-8f);
    float inv = 1.0f / scale;
    if (threadIdx.x == 0) scales[row] = scale;
    for (int j = 0; j < nv; ++j) {
        __half2 h0 = {__float2half_rn(rintf(v[j].x * inv)), __float2half_rn(rintf(v[j].y * inv))};
        __half2 h1 = {__float2half_rn(rintf(v[j].z * inv)), __float2half_rn(rintf(v[j].w * inv))};
        uint2 o;
        o.x = *(uint32_t*)&h0;
        o.y = *(uint32_t*)&h1;
        *(uint2*)&wq[(size_t)row * C + (j * 256 + threadIdx.x) * 4] = o;
    }
}

// ---------------------------------------------------------------------------
// RMSNorm -> fp16, vectorized (float4 in, 2x half2 out). 256 thr, 1 row/block.
// ---------------------------------------------------------------------------
__global__ void rmsnorm_kernel(const float* __restrict__ x,
                               const float* __restrict__ w,
                               __half* __restrict__ out) {
    int row = blockIdx.x;
    const float4* xr = (const float4*)(x + (size_t)row * Dn);
    float4 v4 = xr[threadIdx.x];                  // 256 thr x 4 = 1024
    float ss = v4.x * v4.x + v4.y * v4.y + v4.z * v4.z + v4.w * v4.w;
    __shared__ float sh[32];
    int lane = threadIdx.x & 31, wid = threadIdx.x >> 5;
#pragma unroll
    for (int o = 16; o; o >>= 1) ss += __shfl_xor_sync(0xffffffffu, ss, o);
    if (lane == 0) sh[wid] = ss;
    __syncthreads();
    if (wid == 0) {
        float v = (lane < 8) ? sh[lane] : 0.f;
#pragma unroll
        for (int o = 4; o; o >>= 1) v += __shfl_xor_sync(0xffffffffu, v, o);
        if (lane == 0) sh[0] = v;
    }
    __syncthreads();
    float inv = rsqrtf(sh[0] * (1.0f / Dn) + EPSv);
    float4 w4 = ((const float4*)w)[threadIdx.x];
    __half2 o0 = {__float2half_rn(v4.x * inv * w4.x), __float2half_rn(v4.y * inv * w4.y)};
    __half2 o1 = {__float2half_rn(v4.z * inv * w4.z), __float2half_rn(v4.w * inv * w4.w)};
    uint2 o;
    o.x = *(uint32_t*)&o0;
    o.y = *(uint32_t*)&o1;
    *(uint2*)&out[(size_t)row * Dn + threadIdx.x * 4] = o;
}

// ---------------------------------------------------------------------------
// Causal exp-filter conv (linear recurrence) + SiLU gate, fp16 qkv.
// 32 chunks of 128 steps (warmup 128: alpha^128 = e^-12.8 ~ 3e-6, negligible).
// half2: each thread owns 2 adjacent channels. 256 blocks x 256 threads.
// ---------------------------------------------------------------------------
#define SCH 128
__global__ void scan_gate_kernel(const __half* __restrict__ qkv,
                                 const float* __restrict__ filt,
                                 __half* __restrict__ gated) {
    int tid = threadIdx.x;
    int chunk = blockIdx.x & 31;
    int b = (blockIdx.x >> 5) & 3;
    int cg = blockIdx.x >> 7;                 // 0..1
    int c = cg * 512 + tid * 2;               // even channel; pair same head
    int h = c >> 7;
    float f0 = filt[h];
    float alpha = filt[Hn + h] / f0;
    const __half2* sb = (const __half2*)(qkv + (size_t)b * Tn * MHn + c);
    const __half2* gb = (const __half2*)(qkv + (size_t)b * Tn * MHn + Dn + c);
    __half2* ob = (__half2*)(gated + (size_t)b * Tn * Dn + c);
    const int qs = MHn / 2, os = Dn / 2;
    float y0 = 0.f, y1 = 0.f;
    int t0 = chunk * SCH;
    if (chunk) {
#pragma unroll 4
        for (int t = t0 - SCH; t < t0; ++t) {
            float2 s = __half22float2(__ldg(&sb[(size_t)t * qs]));
            y0 = fmaf(alpha, y0, s.x);
            y1 = fmaf(alpha, y1, s.y);
        }
    }
#pragma unroll 2
    for (int t = t0; t < t0 + SCH; ++t) {
        float2 s = __half22float2(__ldg(&sb[(size_t)t * qs]));
        float2 g = __half22float2(__ldg(&gb[(size_t)t * qs]));
        y0 = fmaf(alpha, y0, s.x);
        y1 = fmaf(alpha, y1, s.y);
        float v0 = (f0 * y0) * (g.x / (1.0f + expf(-g.x)));
        float v1 = (f0 * y1) * (g.y / (1.0f + expf(-g.y)));
        ob[(size_t)t * os] = __floats2half2_rn(v0, v1);
    }
}

// ---------------------------------------------------------------------------
// fp16 tensor-core GEMM: v[m,n] = (sum_k A[m,k]*W[n,k]) * scales[n]
//   EPI 1: Cf = v + Add (fp32)   EPI 2: Ch = fp16(gelu(v))   EPI 3: Ch = fp16(v)
// 128 x BNT tile, 8 warps (4m x 2n; warp tile 32 x BNT/2), BK=32, NST=4,
// prefetch 3, wait_group 2, ONE __syncthreads per iteration, 2 CTAs/SM.
// BNT in {128, 64}. BNT=64 used for N=1024 GEMMs to kill tail waves.
// ---------------------------------------------------------------------------
template <int EPI, int BNT>
__global__ __launch_bounds__(256, 2)
void mma_gemm(const __half* __restrict__ A, const __half* __restrict__ W,
              const float* __restrict__ scales, const float* __restrict__ Add,
              float* __restrict__ Cf, __half* __restrict__ Ch,
              int M, int N, int K) {
    constexpr int STAGE_B = BNT * ASTRIDE * 2;
    constexpr int STAGEB  = STAGE_A + STAGE_B;
    constexpr int NFRAG   = BNT / 16;          // b-frag mma count per ks (8 or 4)
    constexpr int NP      = BNT / 32;          // b ldsm count per ks (4 or 2)

    extern __shared__ char smem[];
    uint32_t s0 = smem_u32(smem);

    int tid = threadIdx.x;
    int bm = blockIdx.y * BM;
    int bn = blockIdx.x * BNT;
    int lane = tid & 31, wid = tid >> 5;
    int wm = wid >> 1, wn = wid & 1;

    int lr = tid >> 2;          // 0..63 load row
    int lc = tid & 3;           // 16B chunk within 64B row

    const __half* Ab = A + (size_t)(bm + lr) * K + lc * 8;
    const __half* Bb = W + (size_t)(bn + lr) * K + lc * 8;
    uint32_t aoff = (uint32_t)(lr * ASTRIDE + lc * 8) * 2;
    const uint32_t rowOfs64 = 64 * ASTRIDE * 2;

    auto load_tile = [&](int kt) {
        uint32_t tb = s0 + (kt & (NST - 1)) * STAGEB;
        const __half* ag = Ab + (size_t)kt * BKh;
        const __half* bg = Bb + (size_t)kt * BKh;
        cpa16(tb + aoff, ag);
        cpa16(tb + aoff + rowOfs64, ag + (size_t)64 * K);
        cpa16(tb + STAGE_A + aoff, bg);
        if (BNT == 128)
            cpa16(tb + STAGE_A + aoff + rowOfs64, bg + (size_t)64 * K);
        cpa_commit();
    };

    float c[2][NFRAG][4];
#pragma unroll
    for (int i = 0; i < 2; ++i)
#pragma unroll
        for (int j = 0; j < NFRAG; ++j)
#pragma unroll
            for (int l = 0; l < 4; ++l) c[i][j][l] = 0.f;

    int KT = K / BKh;
    load_tile(0);
    load_tile(1);
    load_tile(2);

    for (int kt = 0; kt < KT; ++kt) {
        if (kt < KT - 2)       asm volatile("cp.async.wait_group 2;");
        else if (kt == KT - 2) asm volatile("cp.async.wait_group 1;");
        else                   asm volatile("cp.async.wait_group 0;");
        __syncthreads();                    // warps done with kt-1; tile kt visible

        if (kt + 3 < KT) load_tile(kt + 3); // overwrites buffer of kt-1: safe

        uint32_t aBase = s0 + (kt & (NST - 1)) * STAGEB;
        uint32_t bBase = aBase + STAGE_A;
#pragma unroll
        for (int ks = 0; ks < 2; ++ks) {
            uint32_t a[2][4];
#pragma unroll
            for (int mt = 0; mt < 2; ++mt) {
                int row = wm * 32 + mt * 16 + (lane & 15);
                int col = ks * 16 + (lane >> 4) * 8;
                ldsm4(a[mt][0], a[mt][1], a[mt][2], a[mt][3],
                      aBase + (row * ASTRIDE + col) * 2);
            }
            uint32_t b[NP][4];
#pragma unroll
            for (int p = 0; p < NP; ++p) {
                int nrow = wn * (BNT / 2) + p * 16 + (lane & 7) + ((lane >> 4) << 3);
                int col = ks * 16 + ((lane >> 3) & 1) * 8;
                ldsm4(b[p][0], b[p][1], b[p][2], b[p][3],
                      bBase + (nrow * ASTRIDE + col) * 2);
            }
#pragma unroll
            for (int mt = 0; mt < 2; ++mt)
#pragma unroll
                for (int nt = 0; nt < NFRAG; ++nt)
                    mma16816(c[mt][nt], a[mt][0], a[mt][1], a[mt][2], a[mt][3],
                             b[nt >> 1][(nt & 1) * 2], b[nt >> 1][(nt & 1) * 2 + 1]);
        }
    }

    // Epilogue
#pragma unroll
    for (int mt = 0; mt < 2; ++mt) {
#pragma unroll
        for (int nt = 0; nt < NFRAG; ++nt) {
            int r0 = bm + wm * 32 + mt * 16 + (lane >> 2);
            int col = bn + wn * (BNT / 2) + nt * 8 + (lane & 3) * 2;
            float sc0 = __ldg(&scales[col]);
            float sc1 = __ldg(&scales[col + 1]);
#pragma unroll
            for (int half = 0; half < 2; ++half) {
                int row = r0 + half * 8;
                float v0 = c[mt][nt][half * 2 + 0] * sc0;
                float v1 = c[mt][nt][half * 2 + 1] * sc1;
                if (EPI == 1) {
                    float2 r = *(const float2*)&Add[(size_t)row * N + col];
                    float2 o = {v0 + r.x, v1 + r.y};
                    *(float2*)&Cf[(size_t)row * N + col] = o;
                } else if (EPI == 2) {
                    float g0 = 0.5f * v0 * (1.0f + erff(v0 * 0.70710678118654752440f));
                    float g1 = 0.5f * v1 * (1.0f + erff(v1 * 0.70710678118654752440f));
                    __half2 o = {__float2half_rn(g0), __float2half_rn(g1)};
                    *(__half2*)&Ch[(size_t)row * N + col] = o;
                } else {
                    __half2 o = {__float2half_rn(v0), __float2half_rn(v1)};
                    *(__half2*)&Ch[(size_t)row * N + col] = o;
                }
            }
        }
    }
}

#define SMEM_128 (NST * (STAGE_A + 128 * ASTRIDE * 2))   // 81920
#define SMEM_64  (NST * (STAGE_A + 64 * ASTRIDE * 2))    // 61440

// ---------------------------------------------------------------------------
// Launch
// ---------------------------------------------------------------------------
extern "C" void kernel_launch(void* const* d_in, const int* in_sizes, int n_in,
                              void* d_out, int out_size) {
    (void)in_sizes; (void)n_in; (void)out_size;
    const float* x    = (const float*)d_in[0];
    const float* n1w  = (const float*)d_in[1];
    const float* n2w  = (const float*)d_in[2];
    const float* w_in = (const float*)d_in[3];
    const float* w_o  = (const float*)d_in[4];
    const float* w_mi = (const float*)d_in[5];
    const float* w_mo = (const float*)d_in[6];
    const float* filt = (const float*)d_in[7];
    float* out = (float*)d_out;

    __half *p_wq_in, *p_wq_o, *p_wq_mi, *p_wq_mo, *p_h, *p_gated, *p_act;
    float *p_sc_in, *p_sc_o, *p_sc_mi, *p_sc_mo, *p_x2;
    cudaGetSymbolAddress((void**)&p_wq_in, g_wq_in);
    cudaGetSymbolAddress((void**)&p_wq_o,  g_wq_o);
    cudaGetSymbolAddress((void**)&p_wq_mi, g_wq_mi);
    cudaGetSymbolAddress((void**)&p_wq_mo, g_wq_mo);
    cudaGetSymbolAddress((void**)&p_sc_in, g_sc_in);
    cudaGetSymbolAddress((void**)&p_sc_o,  g_sc_o);
    cudaGetSymbolAddress((void**)&p_sc_mi, g_sc_mi);
    cudaGetSymbolAddress((void**)&p_sc_mo, g_sc_mo);
    cudaGetSymbolAddress((void**)&p_h,     g_h);
    cudaGetSymbolAddress((void**)&p_gated, g_gated);
    cudaGetSymbolAddress((void**)&p_act,   g_act);
    cudaGetSymbolAddress((void**)&p_x2,    g_x2);

    cudaFuncSetAttribute(mma_gemm<3,128>, cudaFuncAttributeMaxDynamicSharedMemorySize, SMEM_128);
    cudaFuncSetAttribute(mma_gemm<2,128>, cudaFuncAttributeMaxDynamicSharedMemorySize, SMEM_128);
    cudaFuncSetAttribute(mma_gemm<1,64>,  cudaFuncAttributeMaxDynamicSharedMemorySize, SMEM_64);

    // 1) quantize weights -> exact fp16 integers + scales
    quantize_rows_kernel<<<MHn, 256>>>(w_in, p_wq_in, p_sc_in, Dn);
    quantize_rows_kernel<<<Dn,  256>>>(w_o,  p_wq_o,  p_sc_o,  Dn);
    quantize_rows_kernel<<<MHn, 256>>>(w_mi, p_wq_mi, p_sc_mi, Dn);
    quantize_rows_kernel<<<Dn,  256>>>(w_mo, p_wq_mo, p_sc_mo, MHn);

    // 2) h = rmsnorm(x) -> fp16
    rmsnorm_kernel<<<Mtok, 256>>>(x, n1w, p_h);

    // 3) qkv = h @ Wq_in^T -> fp16 (stored in g_act, dead after scan)
    mma_gemm<3,128><<<dim3(MHn / 128, Mtok / BM), 256, SMEM_128>>>(
        p_h, p_wq_in, p_sc_in, nullptr, nullptr, p_act, Mtok, MHn, Dn);

    // 4) causal conv recurrence + SiLU gate -> fp16
    scan_gate_kernel<<<256, 256>>>(p_act, filt, p_gated);

    // 5) x2 = x + gated @ Wq_o^T (fp32), BN=64 to kill tail waves
    mma_gemm<1,64><<<dim3(Dn / 64, Mtok / BM), 256, SMEM_64>>>(
        p_gated, p_wq_o, p_sc_o, x, p_x2, nullptr, Mtok, Dn, Dn);

    // 6) h2 = rmsnorm(x2) -> fp16
    rmsnorm_kernel<<<Mtok, 256>>>(p_x2, n2w, p_h);

    // 7) m = gelu(h2 @ Wq_mi^T) -> fp16 (overwrites g_act)
    mma_gemm<2,128><<<dim3(MHn / 128, Mtok / BM), 256, SMEM_128>>>(
        p_h, p_wq_mi, p_sc_mi, nullptr, nullptr, p_act, Mtok, MHn, Dn);

    // 8) out = x2 + m @ Wq_mo^T (fp32), BN=64 to kill tail waves
    mma_gemm<1,64><<<dim3(Dn / 64, Mtok / BM), 256, SMEM_64>>>(
        p_act, p_wq_mo, p_sc_mo, p_x2, out, nullptr, Mtok, Dn, MHn);
}

// round 12
// speedup vs baseline: 1.4480x; 1.0191x over previous
#include <cuda_runtime.h>
#include <cuda_fp16.h>
#include <math.h>
#include <stdint.h>

// Problem constants
#define Bsz   4
#define Tn    4096
#define Dn    1024
#define Hn    8
#define MHn   2048
#define Mtok  (Bsz * Tn)          // 16384 tokens
#define EPSv  1e-6f

// GEMM tile config (proven): 128(M) x BNT(N) CTA tile, BK=32/stage, NST=4,
// prefetch distance 3, wait_group 2, ONE sync per iteration.
#define BM 128
#define BKh 32                     // K-halves per stage
#define NST 4                      // pipeline stages
#define ASTRIDE 40                 // smem row stride in halves -> conflict-free ldmatrix
#define STAGE_A  (BM * ASTRIDE * 2)             // 10240 B

// ---------------------------------------------------------------------------
// Device-global scratch (no cudaMalloc).  Weights: exact-integer fp16 [N,K].
// g_act doubles as the qkv buffer (qkv dead after scan; act written after).
// ---------------------------------------------------------------------------
__device__ __half g_wq_in[(size_t)MHn * Dn];
__device__ __half g_wq_o [(size_t)Dn  * Dn];
__device__ __half g_wq_mi[(size_t)MHn * Dn];
__device__ __half g_wq_mo[(size_t)Dn  * MHn];
__device__ float g_sc_in[MHn];
__device__ float g_sc_o [Dn];
__device__ float g_sc_mi[MHn];
__device__ float g_sc_mo[Dn];
__device__ __half g_h    [(size_t)Mtok * Dn];    // rmsnorm out (reused for h2)
__device__ __half g_gated[(size_t)Mtok * Dn];    // gated fp16
__device__ __half g_act  [(size_t)Mtok * MHn];   // qkv fp16, then gelu out fp16
__device__ float  g_x2   [(size_t)Mtok * Dn];    // post-attn residual

// ---------------------------------------------------------------------------
// PTX helpers
// ---------------------------------------------------------------------------
__device__ __forceinline__ uint32_t smem_u32(const void* p) {
    return (uint32_t)__cvta_generic_to_shared(p);
}
__device__ __forceinline__ void cpa16(uint32_t s, const void* g) {
    asm volatile("cp.async.cg.shared.global [%0], [%1], 16;" :: "r"(s), "l"(g));
}
__device__ __forceinline__ void cpa_commit() {
    asm volatile("cp.async.commit_group;");
}
__device__ __forceinline__ void ldsm4(uint32_t& r0, uint32_t& r1, uint32_t& r2, uint32_t& r3,
                                      uint32_t addr) {
    asm volatile("ldmatrix.sync.aligned.m8n8.x4.shared.b16 {%0,%1,%2,%3}, [%4];"
                 : "=r"(r0), "=r"(r1), "=r"(r2), "=r"(r3) : "r"(addr));
}
__device__ __forceinline__ void mma16816(float* c, uint32_t a0, uint32_t a1, uint32_t a2,
                                         uint32_t a3, uint32_t b0, uint32_t b1) {
    asm volatile("mma.sync.aligned.m16n8k16.row.col.f32.f16.f16.f32 "
                 "{%0,%1,%2,%3}, {%4,%5,%6,%7}, {%8,%9}, {%0,%1,%2,%3};"
                 : "+f"(c[0]), "+f"(c[1]), "+f"(c[2]), "+f"(c[3])
                 : "r"(a0), "r"(a1), "r"(a2), "r"(a3), "r"(b0), "r"(b1));
}

// ---------------------------------------------------------------------------
// Quantize (register-resident single pass):
// wq[n,k] = fp16(round(w/scale)) exact integers; scales[n] = scale.
// ---------------------------------------------------------------------------
__global__ void quantize_rows_kernel(const float* __restrict__ w,
                                     __half* __restrict__ wq,
                                     float* __restrict__ scales, int C) {
    int row = blockIdx.x;
    int nv = C >> 10;                       // 1 (C=1024) or 2 (C=2048)
    const float4* wr = (const float4*)(w + (size_t)row * C);
    float4 v[2];
    float m = 0.f;
    for (int j = 0; j < nv; ++j) {
        v[j] = wr[j * 256 + threadIdx.x];
        m = fmaxf(m, fmaxf(fmaxf(fabsf(v[j].x), fabsf(v[j].y)),
                           fmaxf(fabsf(v[j].z), fabsf(v[j].w))));
    }
    __shared__ float sh[32];
    int lane = threadIdx.x & 31, wid = threadIdx.x >> 5;
#pragma unroll
    for (int o = 16; o; o >>= 1) m = fmaxf(m, __shfl_xor_sync(0xffffffffu, m, o));
    if (lane == 0) sh[wid] = m;
    __syncthreads();
    if (wid == 0) {
        float t = (lane < 8) ? sh[lane] : 0.f;
#pragma unroll
        for (int o = 4; o; o >>= 1) t = fmaxf(t, __shfl_xor_sync(0xffffffffu, t, o));
        if (lane == 0) sh[0] = t;
    }
    __syncthreads();
    float scale = fmaxf(sh[0] * (1.0f / 127.0f), 1e-8f);
    float inv = 1.0f / scale;
    if (threadIdx.x == 0) scales[row] = scale;
    for (int j = 0; j < nv; ++j) {
        __half2 h0 = {__float2half_rn(rintf(v[j].x * inv)), __float2half_rn(rintf(v[j].y * inv))};
        __half2 h1 = {__float2half_rn(rintf(v[j].z * inv)), __float2half_rn(rintf(v[j].w * inv))};
        uint2 o;
        o.x = *(uint32_t*)&h0;
        o.y = *(uint32_t*)&h1;
        *(uint2*)&wq[(size_t)row * C + (j * 256 + threadIdx.x) * 4] = o;
    }
}

// ---------------------------------------------------------------------------
// RMSNorm -> fp16, vectorized (float4 in, 2x half2 out). 256 thr, 1 row/block.
// ---------------------------------------------------------------------------
__global__ void rmsnorm_kernel(const float* __restrict__ x,
                               const float* __restrict__ w,
                               __half* __restrict__ out) {
    int row = blockIdx.x;
    const float4* xr = (const float4*)(x + (size_t)row * Dn);
    float4 v4 = xr[threadIdx.x];                  // 256 thr x 4 = 1024
    float ss = v4.x * v4.x + v4.y * v4.y + v4.z * v4.z + v4.w * v4.w;
    __shared__ float sh[32];
    int lane = threadIdx.x & 31, wid = threadIdx.x >> 5;
#pragma unroll
    for (int o = 16; o; o >>= 1) ss += __shfl_xor_sync(0xffffffffu, ss, o);
    if (lane == 0) sh[wid] = ss;
    __syncthreads();
    if (wid == 0) {
        float v = (lane < 8) ? sh[lane] : 0.f;
#pragma unroll
        for (int o = 4; o; o >>= 1) v += __shfl_xor_sync(0xffffffffu, v, o);
        if (lane == 0) sh[0] = v;
    }
    __syncthreads();
    float inv = rsqrtf(sh[0] * (1.0f / Dn) + EPSv);
    float4 w4 = ((const float4*)w)[threadIdx.x];
    __half2 o0 = {__float2half_rn(v4.x * inv * w4.x), __float2half_rn(v4.y * inv * w4.y)};
    __half2 o1 = {__float2half_rn(v4.z * inv * w4.z), __float2half_rn(v4.w * inv * w4.w)};
    uint2 o;
    o.x = *(uint32_t*)&o0;
    o.y = *(uint32_t*)&o1;
    *(uint2*)&out[(size_t)row * Dn + threadIdx.x * 4] = o;
}

// ---------------------------------------------------------------------------
// Causal exp-filter conv (linear recurrence) + SiLU gate, fp16 qkv.
// 32 chunks of 128 steps (warmup 128: alpha^128 = e^-12.8 ~ 3e-6, negligible).
// half2: each thread owns 2 adjacent channels. 256 blocks x 256 threads.
// ---------------------------------------------------------------------------
#define SCH 128
__global__ void scan_gate_kernel(const __half* __restrict__ qkv,
                                 const float* __restrict__ filt,
                                 __half* __restrict__ gated) {
    int tid = threadIdx.x;
    int chunk = blockIdx.x & 31;
    int b = (blockIdx.x >> 5) & 3;
    int cg = blockIdx.x >> 7;                 // 0..1
    int c = cg * 512 + tid * 2;               // even channel; pair same head
    int h = c >> 7;
    float f0 = filt[h];
    float alpha = filt[Hn + h] / f0;
    const __half2* sb = (const __half2*)(qkv + (size_t)b * Tn * MHn + c);
    const __half2* gb = (const __half2*)(qkv + (size_t)b * Tn * MHn + Dn + c);
    __half2* ob = (__half2*)(gated + (size_t)b * Tn * Dn + c);
    const int qs = MHn / 2, os = Dn / 2;
    float y0 = 0.f, y1 = 0.f;
    int t0 = chunk * SCH;
    if (chunk) {
#pragma unroll 4
        for (int t = t0 - SCH; t < t0; ++t) {
            float2 s = __half22float2(__ldg(&sb[(size_t)t * qs]));
            y0 = fmaf(alpha, y0, s.x);
            y1 = fmaf(alpha, y1, s.y);
        }
    }
#pragma unroll 2
    for (int t = t0; t < t0 + SCH; ++t) {
        float2 s = __half22float2(__ldg(&sb[(size_t)t * qs]));
        float2 g = __half22float2(__ldg(&gb[(size_t)t * qs]));
        y0 = fmaf(alpha, y0, s.x);
        y1 = fmaf(alpha, y1, s.y);
        float v0 = (f0 * y0) * (g.x / (1.0f + expf(-g.x)));
        float v1 = (f0 * y1) * (g.y / (1.0f + expf(-g.y)));
        ob[(size_t)t * os] = __floats2half2_rn(v0, v1);
    }
}

// ---------------------------------------------------------------------------
// fp16 tensor-core GEMM: v[m,n] = (sum_k A[m,k]*W[n,k]) * scales[n]
//   EPI 1: Cf = v + Add (fp32)   EPI 2: Ch = fp16(gelu(v))   EPI 3: Ch = fp16(v)
// 128 x BNT tile, 8 warps (4m x 2n; warp tile 32 x BNT/2), BK=32, NST=4,
// prefetch 3, wait_group 2, ONE __syncthreads per iteration.
// BNT=128 -> 2 CTAs/SM;  BNT=64 -> 3 CTAs/SM (smem 3x61440=184KB fits).
// ---------------------------------------------------------------------------
template <int EPI, int BNT>
__global__ __launch_bounds__(256, (BNT == 64) ? 3 : 2)
void mma_gemm(const __half* __restrict__ A, const __half* __restrict__ W,
              const float* __restrict__ scales, const float* __restrict__ Add,
              float* __restrict__ Cf, __half* __restrict__ Ch,
              int M, int N, int K) {
    constexpr int STAGE_B = BNT * ASTRIDE * 2;
    constexpr int STAGEB  = STAGE_A + STAGE_B;
    constexpr int NFRAG   = BNT / 16;          // b-frag mma count per ks (8 or 4)
    constexpr int NP      = BNT / 32;          // b ldsm count per ks (4 or 2)

    extern __shared__ char smem[];
    uint32_t s0 = smem_u32(smem);

    int tid = threadIdx.x;
    int bm = blockIdx.y * BM;
    int bn = blockIdx.x * BNT;
    int lane = tid & 31, wid = tid >> 5;
    int wm = wid >> 1, wn = wid & 1;

    int lr = tid >> 2;          // 0..63 load row
    int lc = tid & 3;           // 16B chunk within 64B row

    const __half* Ab = A + (size_t)(bm + lr) * K + lc * 8;
    const __half* Bb = W + (size_t)(bn + lr) * K + lc * 8;
    uint32_t aoff = (uint32_t)(lr * ASTRIDE + lc * 8) * 2;
    const uint32_t rowOfs64 = 64 * ASTRIDE * 2;

    auto load_tile = [&](int kt) {
        uint32_t tb = s0 + (kt & (NST - 1)) * STAGEB;
        const __half* ag = Ab + (size_t)kt * BKh;
        const __half* bg = Bb + (size_t)kt * BKh;
        cpa16(tb + aoff, ag);
        cpa16(tb + aoff + rowOfs64, ag + (size_t)64 * K);
        cpa16(tb + STAGE_A + aoff, bg);
        if (BNT == 128)
            cpa16(tb + STAGE_A + aoff + rowOfs64, bg + (size_t)64 * K);
        cpa_commit();
    };

    float c[2][NFRAG][4];
#pragma unroll
    for (int i = 0; i < 2; ++i)
#pragma unroll
        for (int j = 0; j < NFRAG; ++j)
#pragma unroll
            for (int l = 0; l < 4; ++l) c[i][j][l] = 0.f;

    int KT = K / BKh;
    load_tile(0);
    load_tile(1);
    load_tile(2);

    for (int kt = 0; kt < KT; ++kt) {
        if (kt < KT - 2)       asm volatile("cp.async.wait_group 2;");
        else if (kt == KT - 2) asm volatile("cp.async.wait_group 1;");
        else                   asm volatile("cp.async.wait_group 0;");
        __syncthreads();                    // warps done with kt-1; tile kt visible

        if (kt + 3 < KT) load_tile(kt + 3); // overwrites buffer of kt-1: safe

        uint32_t aBase = s0 + (kt & (NST - 1)) * STAGEB;
        uint32_t bBase = aBase + STAGE_A;
#pragma unroll
        for (int ks = 0; ks < 2; ++ks) {
            uint32_t a[2][4];
#pragma unroll
            for (int mt = 0; mt < 2; ++mt) {
                int row = wm * 32 + mt * 16 + (lane & 15);
                int col = ks * 16 + (lane >> 4) * 8;
                ldsm4(a[mt][0], a[mt][1], a[mt][2], a[mt][3],
                      aBase + (row * ASTRIDE + col) * 2);
            }
            uint32_t b[NP][4];
#pragma unroll
            for (int p = 0; p < NP; ++p) {
                int nrow = wn * (BNT / 2) + p * 16 + (lane & 7) + ((lane >> 4) << 3);
                int col = ks * 16 + ((lane >> 3) & 1) * 8;
                ldsm4(b[p][0], b[p][1], b[p][2], b[p][3],
                      bBase + (nrow * ASTRIDE + col) * 2);
            }
#pragma unroll
            for (int mt = 0; mt < 2; ++mt)
#pragma unroll
                for (int nt = 0; nt < NFRAG; ++nt)
                    mma16816(c[mt][nt], a[mt][0], a[mt][1], a[mt][2], a[mt][3],
                             b[nt >> 1][(nt & 1) * 2], b[nt >> 1][(nt & 1) * 2 + 1]);
        }
    }

    // Epilogue
#pragma unroll
    for (int mt = 0; mt < 2; ++mt) {
#pragma unroll
        for (int nt = 0; nt < NFRAG; ++nt) {
            int r0 = bm + wm * 32 + mt * 16 + (lane >> 2);
            int col = bn + wn * (BNT / 2) + nt * 8 + (lane & 3) * 2;
            float sc0 = __ldg(&scales[col]);
            float sc1 = __ldg(&scales[col + 1]);
#pragma unroll
            for (int half = 0; half < 2; ++half) {
                int row = r0 + half * 8;
                float v0 = c[mt][nt][half * 2 + 0] * sc0;
                float v1 = c[mt][nt][half * 2 + 1] * sc1;
                if (EPI == 1) {
                    float2 r = *(const float2*)&Add[(size_t)row * N + col];
                    float2 o = {v0 + r.x, v1 + r.y};
                    *(float2*)&Cf[(size_t)row * N + col] = o;
                } else if (EPI == 2) {
                    float g0 = 0.5f * v0 * (1.0f + erff(v0 * 0.70710678118654752440f));
                    float g1 = 0.5f * v1 * (1.0f + erff(v1 * 0.70710678118654752440f));
                    __half2 o = {__float2half_rn(g0), __float2half_rn(g1)};
                    *(__half2*)&Ch[(size_t)row * N + col] = o;
                } else {
                    __half2 o = {__float2half_rn(v0), __float2half_rn(v1)};
                    *(__half2*)&Ch[(size_t)row * N + col] = o;
                }
            }
        }
    }
}

#define SMEM_128 (NST * (STAGE_A + 128 * ASTRIDE * 2))   // 81920
#define SMEM_64  (NST * (STAGE_A + 64 * ASTRIDE * 2))    // 61440

// ---------------------------------------------------------------------------
// Launch.  Quantize kernels run on a forked side-stream (captured via the
// documented event fork-join pattern) so they overlap rmsnorm1 + GEMM-3.
// Stream/event create/destroy are host-side ops (not captured, no dev allocs).
// ---------------------------------------------------------------------------
extern "C" void kernel_launch(void* const* d_in, const int* in_sizes, int n_in,
                              void* d_out, int out_size) {
    (void)in_sizes; (void)n_in; (void)out_size;
    const float* x    = (const float*)d_in[0];
    const float* n1w  = (const float*)d_in[1];
    const float* n2w  = (const float*)d_in[2];
    const float* w_in = (const float*)d_in[3];
    const float* w_o  = (const float*)d_in[4];
    const float* w_mi = (const float*)d_in[5];
    const float* w_mo = (const float*)d_in[6];
    const float* filt = (const float*)d_in[7];
    float* out = (float*)d_out;

    __half *p_wq_in, *p_wq_o, *p_wq_mi, *p_wq_mo, *p_h, *p_gated, *p_act;
    float *p_sc_in, *p_sc_o, *p_sc_mi, *p_sc_mo, *p_x2;
    cudaGetSymbolAddress((void**)&p_wq_in, g_wq_in);
    cudaGetSymbolAddress((void**)&p_wq_o,  g_wq_o);
    cudaGetSymbolAddress((void**)&p_wq_mi, g_wq_mi);
    cudaGetSymbolAddress((void**)&p_wq_mo, g_wq_mo);
    cudaGetSymbolAddress((void**)&p_sc_in, g_sc_in);
    cudaGetSymbolAddress((void**)&p_sc_o,  g_sc_o);
    cudaGetSymbolAddress((void**)&p_sc_mi, g_sc_mi);
    cudaGetSymbolAddress((void**)&p_sc_mo, g_sc_mo);
    cudaGetSymbolAddress((void**)&p_h,     g_h);
    cudaGetSymbolAddress((void**)&p_gated, g_gated);
    cudaGetSymbolAddress((void**)&p_act,   g_act);
    cudaGetSymbolAddress((void**)&p_x2,    g_x2);

    cudaFuncSetAttribute(mma_gemm<3,128>, cudaFuncAttributeMaxDynamicSharedMemorySize, SMEM_128);
    cudaFuncSetAttribute(mma_gemm<2,128>, cudaFuncAttributeMaxDynamicSharedMemorySize, SMEM_128);
    cudaFuncSetAttribute(mma_gemm<1,64>,  cudaFuncAttributeMaxDynamicSharedMemorySize, SMEM_64);

    cudaStream_t s2;
    cudaEvent_t evFork, evQIn, evQRest;
    cudaStreamCreateWithFlags(&s2, cudaStreamNonBlocking);
    cudaEventCreateWithFlags(&evFork,  cudaEventDisableTiming);
    cudaEventCreateWithFlags(&evQIn,   cudaEventDisableTiming);
    cudaEventCreateWithFlags(&evQRest, cudaEventDisableTiming);

    // Fork: side stream joins the capture via event dependency.
    cudaEventRecord(evFork, 0);
    cudaStreamWaitEvent(s2, evFork, 0);

    // Side stream: all weight quantization (overlaps rmsnorm1 + GEMM-3).
    quantize_rows_kernel<<<MHn, 256, 0, s2>>>(w_in, p_wq_in, p_sc_in, Dn);
    cudaEventRecord(evQIn, s2);
    quantize_rows_kernel<<<Dn,  256, 0, s2>>>(w_o,  p_wq_o,  p_sc_o,  Dn);
    quantize_rows_kernel<<<MHn, 256, 0, s2>>>(w_mi, p_wq_mi, p_sc_mi, Dn);
    quantize_rows_kernel<<<Dn,  256, 0, s2>>>(w_mo, p_wq_mo, p_sc_mo, MHn);
    cudaEventRecord(evQRest, s2);

    // Main stream: 2) h = rmsnorm(x) -> fp16  (independent of quantize)
    rmsnorm_kernel<<<Mtok, 256>>>(x, n1w, p_h);

    // Join #1: GEMM-3 needs wq_in.
    cudaStreamWaitEvent(0, evQIn, 0);

    // 3) qkv = h @ Wq_in^T -> fp16 (stored in g_act, dead after scan)
    mma_gemm<3,128><<<dim3(MHn / 128, Mtok / BM), 256, SMEM_128>>>(
        p_h, p_wq_in, p_sc_in, nullptr, nullptr, p_act, Mtok, MHn, Dn);

    // 4) causal conv recurrence + SiLU gate -> fp16
    scan_gate_kernel<<<256, 256>>>(p_act, filt, p_gated);

    // Join #2: remaining GEMMs need wq_o / wq_mi / wq_mo.
    cudaStreamWaitEvent(0, evQRest, 0);

    // 5) x2 = x + gated @ Wq_o^T (fp32), BN=64, 3 CTAs/SM
    mma_gemm<1,64><<<dim3(Dn / 64, Mtok / BM), 256, SMEM_64>>>(
        p_gated, p_wq_o, p_sc_o, x, p_x2, nullptr, Mtok, Dn, Dn);

    // 6) h2 = rmsnorm(x2) -> fp16
    rmsnorm_kernel<<<Mtok, 256>>>(p_x2, n2w, p_h);

    // 7) m = gelu(h2 @ Wq_mi^T) -> fp16 (overwrites g_act)
    mma_gemm<2,128><<<dim3(MHn / 128, Mtok / BM), 256, SMEM_128>>>(
        p_h, p_wq_mi, p_sc_mi, nullptr, nullptr, p_act, Mtok, MHn, Dn);

    // 8) out = x2 + m @ Wq_mo^T (fp32), BN=64, 3 CTAs/SM
    mma_gemm<1,64><<<dim3(Dn / 64, Mtok / BM), 256, SMEM_64>>>(
        p_act, p_wq_mo, p_sc_mo, p_x2, out, nullptr, Mtok, Dn, MHn);

    // Host-side cleanup (not captured; graph retains the dependencies).
    cudaStreamDestroy(s2);
    cudaEventDestroy(evFork);
    cudaEventDestroy(evQIn);
    cudaEventDestroy(evQRest);
}

// round 15
// speedup vs baseline: 1.4564x; 1.0058x over previous
#include <cuda_runtime.h>
#include <cuda_fp16.h>
#include <math.h>
#include <stdint.h>

// Problem constants
#define Bsz   4
#define Tn    4096
#define Dn    1024
#define Hn    8
#define MHn   2048
#define Mtok  (Bsz * Tn)          // 16384 tokens
#define EPSv  1e-6f

// GEMM tile config (proven): 128(M) x BNT(N) CTA tile, BK=32/stage, NST=4,
// prefetch distance 3, wait_group 2, ONE sync per iteration.
#define BM 128
#define BKh 32                     // K-halves per stage
#define NST 4                      // pipeline stages
#define ASTRIDE 40                 // smem row stride in halves -> conflict-free ldmatrix
#define STAGE_A  (BM * ASTRIDE * 2)             // 10240 B

// ---------------------------------------------------------------------------
// Device-global scratch (no cudaMalloc).  Weights: exact-integer fp16 [N,K].
// g_act doubles as the qkv buffer (qkv dead after scan; act written after).
// Residual stream x2 now fp16 (error budget allows; saves 96 MB traffic).
// ---------------------------------------------------------------------------
__device__ __half g_wq_in[(size_t)MHn * Dn];
__device__ __half g_wq_o [(size_t)Dn  * Dn];
__device__ __half g_wq_mi[(size_t)MHn * Dn];
__device__ __half g_wq_mo[(size_t)Dn  * MHn];
__device__ float g_sc_in[MHn];
__device__ float g_sc_o [Dn];
__device__ float g_sc_mi[MHn];
__device__ float g_sc_mo[Dn];
__device__ __half g_h    [(size_t)Mtok * Dn];    // rmsnorm out (reused for h2)
__device__ __half g_gated[(size_t)Mtok * Dn];    // gated fp16
__device__ __half g_act  [(size_t)Mtok * MHn];   // qkv fp16, then gelu out fp16
__device__ __half g_x2   [(size_t)Mtok * Dn];    // post-attn residual (fp16)

// ---------------------------------------------------------------------------
// PTX helpers
// ---------------------------------------------------------------------------
__device__ __forceinline__ uint32_t smem_u32(const void* p) {
    return (uint32_t)__cvta_generic_to_shared(p);
}
__device__ __forceinline__ void cpa16(uint32_t s, const void* g) {
    asm volatile("cp.async.cg.shared.global [%0], [%1], 16;" :: "r"(s), "l"(g));
}
__device__ __forceinline__ void cpa_commit() {
    asm volatile("cp.async.commit_group;");
}
__device__ __forceinline__ void ldsm4(uint32_t& r0, uint32_t& r1, uint32_t& r2, uint32_t& r3,
                                      uint32_t addr) {
    asm volatile("ldmatrix.sync.aligned.m8n8.x4.shared.b16 {%0,%1,%2,%3}, [%4];"
                 : "=r"(r0), "=r"(r1), "=r"(r2), "=r"(r3) : "r"(addr));
}
__device__ __forceinline__ void mma16816(float* c, uint32_t a0, uint32_t a1, uint32_t a2,
                                         uint32_t a3, uint32_t b0, uint32_t b1) {
    asm volatile("mma.sync.aligned.m16n8k16.row.col.f32.f16.f16.f32 "
                 "{%0,%1,%2,%3}, {%4,%5,%6,%7}, {%8,%9}, {%0,%1,%2,%3};"
                 : "+f"(c[0]), "+f"(c[1]), "+f"(c[2]), "+f"(c[3])
                 : "r"(a0), "r"(a1), "r"(a2), "r"(a3), "r"(b0), "r"(b1));
}

// ---------------------------------------------------------------------------
// Quantize (register-resident single pass):
// wq[n,k] = fp16(round(w/scale)) exact integers; scales[n] = scale.
// ---------------------------------------------------------------------------
__global__ void quantize_rows_kernel(const float* __restrict__ w,
                                     __half* __restrict__ wq,
                                     float* __restrict__ scales, int C) {
    int row = blockIdx.x;
    int nv = C >> 10;                       // 1 (C=1024) or 2 (C=2048)
    const float4* wr = (const float4*)(w + (size_t)row * C);
    float4 v[2];
    float m = 0.f;
    for (int j = 0; j < nv; ++j) {
        v[j] = wr[j * 256 + threadIdx.x];
        m = fmaxf(m, fmaxf(fmaxf(fabsf(v[j].x), fabsf(v[j].y)),
                           fmaxf(fabsf(v[j].z), fabsf(v[j].w))));
    }
    __shared__ float sh[32];
    int lane = threadIdx.x & 31, wid = threadIdx.x >> 5;
#pragma unroll
    for (int o = 16; o; o >>= 1) m = fmaxf(m, __shfl_xor_sync(0xffffffffu, m, o));
    if (lane == 0) sh[wid] = m;
    __syncthreads();
    if (wid == 0) {
        float t = (lane < 8) ? sh[lane] : 0.f;
#pragma unroll
        for (int o = 4; o; o >>= 1) t = fmaxf(t, __shfl_xor_sync(0xffffffffu, t, o));
        if (lane == 0) sh[0] = t;
    }
    __syncthreads();
    float scale = fmaxf(sh[0] * (1.0f / 127.0f), 1e-8f);
    float inv = 1.0f / scale;
    if (threadIdx.x == 0) scales[row] = scale;
    for (int j = 0; j < nv; ++j) {
        __half2 h0 = {__float2half_rn(rintf(v[j].x * inv)), __float2half_rn(rintf(v[j].y * inv))};
        __half2 h1 = {__float2half_rn(rintf(v[j].z * inv)), __float2half_rn(rintf(v[j].w * inv))};
        uint2 o;
        o.x = *(uint32_t*)&h0;
        o.y = *(uint32_t*)&h1;
        *(uint2*)&wq[(size_t)row * C + (j * 256 + threadIdx.x) * 4] = o;
    }
}

// ---------------------------------------------------------------------------
// RMSNorm (fp32 input) -> fp16.  256 thr, 1 row/block, fully vectorized.
// ---------------------------------------------------------------------------
__global__ void rmsnorm_kernel(const float* __restrict__ x,
                               const float* __restrict__ w,
                               __half* __restrict__ out) {
    int row = blockIdx.x;
    const float4* xr = (const float4*)(x + (size_t)row * Dn);
    float4 v4 = xr[threadIdx.x];
    float ss = v4.x * v4.x + v4.y * v4.y + v4.z * v4.z + v4.w * v4.w;
    __shared__ float sh[32];
    int lane = threadIdx.x & 31, wid = threadIdx.x >> 5;
#pragma unroll
    for (int o = 16; o; o >>= 1) ss += __shfl_xor_sync(0xffffffffu, ss, o);
    if (lane == 0) sh[wid] = ss;
    __syncthreads();
    if (wid == 0) {
        float v = (lane < 8) ? sh[lane] : 0.f;
#pragma unroll
        for (int o = 4; o; o >>= 1) v += __shfl_xor_sync(0xffffffffu, v, o);
        if (lane == 0) sh[0] = v;
    }
    __syncthreads();
    float inv = rsqrtf(sh[0] * (1.0f / Dn) + EPSv);
    float4 w4 = ((const float4*)w)[threadIdx.x];
    __half2 o0 = {__float2half_rn(v4.x * inv * w4.x), __float2half_rn(v4.y * inv * w4.y)};
    __half2 o1 = {__float2half_rn(v4.z * inv * w4.z), __float2half_rn(v4.w * inv * w4.w)};
    uint2 o;
    o.x = *(uint32_t*)&o0;
    o.y = *(uint32_t*)&o1;
    *(uint2*)&out[(size_t)row * Dn + threadIdx.x * 4] = o;
}

// ---------------------------------------------------------------------------
// RMSNorm (fp16 input) -> fp16.  For the fp16 residual stream x2.
// ---------------------------------------------------------------------------
__global__ void rmsnorm_h_kernel(const __half* __restrict__ x,
                                 const float* __restrict__ w,
                                 __half* __restrict__ out) {
    int row = blockIdx.x;
    uint2 raw = *(const uint2*)&x[(size_t)row * Dn + threadIdx.x * 4];
    __half2 x0 = *(__half2*)&raw.x;
    __half2 x1 = *(__half2*)&raw.y;
    float2 f0 = __half22float2(x0);
    float2 f1 = __half22float2(x1);
    float ss = f0.x * f0.x + f0.y * f0.y + f1.x * f1.x + f1.y * f1.y;
    __shared__ float sh[32];
    int lane = threadIdx.x & 31, wid = threadIdx.x >> 5;
#pragma unroll
    for (int o = 16; o; o >>= 1) ss += __shfl_xor_sync(0xffffffffu, ss, o);
    if (lane == 0) sh[wid] = ss;
    __syncthreads();
    if (wid == 0) {
        float v = (lane < 8) ? sh[lane] : 0.f;
#pragma unroll
        for (int o = 4; o; o >>= 1) v += __shfl_xor_sync(0xffffffffu, v, o);
        if (lane == 0) sh[0] = v;
    }
    __syncthreads();
    float inv = rsqrtf(sh[0] * (1.0f / Dn) + EPSv);
    float4 w4 = ((const float4*)w)[threadIdx.x];
    __half2 o0 = {__float2half_rn(f0.x * inv * w4.x), __float2half_rn(f0.y * inv * w4.y)};
    __half2 o1 = {__float2half_rn(f1.x * inv * w4.z), __float2half_rn(f1.y * inv * w4.w)};
    uint2 o;
    o.x = *(uint32_t*)&o0;
    o.y = *(uint32_t*)&o1;
    *(uint2*)&out[(size_t)row * Dn + threadIdx.x * 4] = o;
}

// ---------------------------------------------------------------------------
// Causal exp-filter conv (linear recurrence) + SiLU gate, fp16 qkv.
// 32 chunks of 128 steps (warmup 128: alpha^128 = e^-12.8 ~ 3e-6, negligible).
// half2: each thread owns 2 adjacent channels. 256 blocks x 256 threads.
// ---------------------------------------------------------------------------
#define SCH 128
__global__ void scan_gate_kernel(const __half* __restrict__ qkv,
                                 const float* __restrict__ filt,
                                 __half* __restrict__ gated) {
    int tid = threadIdx.x;
    int chunk = blockIdx.x & 31;
    int b = (blockIdx.x >> 5) & 3;
    int cg = blockIdx.x >> 7;                 // 0..1
    int c = cg * 512 + tid * 2;               // even channel; pair same head
    int h = c >> 7;
    float f0 = filt[h];
    float alpha = filt[Hn + h] / f0;
    const __half2* sb = (const __half2*)(qkv + (size_t)b * Tn * MHn + c);
    const __half2* gb = (const __half2*)(qkv + (size_t)b * Tn * MHn + Dn + c);
    __half2* ob = (__half2*)(gated + (size_t)b * Tn * Dn + c);
    const int qs = MHn / 2, os = Dn / 2;
    float y0 = 0.f, y1 = 0.f;
    int t0 = chunk * SCH;
    if (chunk) {
#pragma unroll 4
        for (int t = t0 - SCH; t < t0; ++t) {
            float2 s = __half22float2(__ldg(&sb[(size_t)t * qs]));
            y0 = fmaf(alpha, y0, s.x);
            y1 = fmaf(alpha, y1, s.y);
        }
    }
#pragma unroll 2
    for (int t = t0; t < t0 + SCH; ++t) {
        float2 s = __half22float2(__ldg(&sb[(size_t)t * qs]));
        float2 g = __half22float2(__ldg(&gb[(size_t)t * qs]));
        y0 = fmaf(alpha, y0, s.x);
        y1 = fmaf(alpha, y1, s.y);
        float v0 = (f0 * y0) * (g.x / (1.0f + __expf(-g.x)));
        float v1 = (f0 * y1) * (g.y / (1.0f + __expf(-g.y)));
        ob[(size_t)t * os] = __floats2half2_rn(v0, v1);
    }
}

// ---------------------------------------------------------------------------
// fp16 tensor-core GEMM: v[m,n] = (sum_k A[m,k]*W[n,k]) * scales[n]
//   EPI 2: Ch = fp16(gelu(v))       EPI 3: Ch = fp16(v)
//   EPI 4: Ch = fp16(v + Addf)      EPI 5: Cf = v + Addh (fp32 out)
// 128 x BNT tile, 8 warps (4m x 2n; warp tile 32 x BNT/2), BK=32, NST=4,
// prefetch 3, wait_group 2, ONE __syncthreads per iteration.
// BNT=128 -> 2 CTAs/SM;  BNT=64 -> 3 CTAs/SM.
// ---------------------------------------------------------------------------
template <int EPI, int BNT>
__global__ __launch_bounds__(256, (BNT == 64) ? 3 : 2)
void mma_gemm(const __half* __restrict__ A, const __half* __restrict__ W,
              const float* __restrict__ scales,
              const float* __restrict__ Addf, const __half* __restrict__ Addh,
              float* __restrict__ Cf, __half* __restrict__ Ch,
              int M, int N, int K) {
    constexpr int STAGE_B = BNT * ASTRIDE * 2;
    constexpr int STAGEB  = STAGE_A + STAGE_B;
    constexpr int NFRAG   = BNT / 16;
    constexpr int NP      = BNT / 32;

    extern __shared__ char smem[];
    uint32_t s0 = smem_u32(smem);

    int tid = threadIdx.x;
    int bm = blockIdx.y * BM;
    int bn = blockIdx.x * BNT;
    int lane = tid & 31, wid = tid >> 5;
    int wm = wid >> 1, wn = wid & 1;

    int lr = tid >> 2;          // 0..63 load row
    int lc = tid & 3;           // 16B chunk within 64B row

    const __half* Ab = A + (size_t)(bm + lr) * K + lc * 8;
    const __half* Bb = W + (size_t)(bn + lr) * K + lc * 8;
    uint32_t aoff = (uint32_t)(lr * ASTRIDE + lc * 8) * 2;
    const uint32_t rowOfs64 = 64 * ASTRIDE * 2;

    auto load_tile = [&](int kt) {
        uint32_t tb = s0 + (kt & (NST - 1)) * STAGEB;
        const __half* ag = Ab + (size_t)kt * BKh;
        const __half* bg = Bb + (size_t)kt * BKh;
        cpa16(tb + aoff, ag);
        cpa16(tb + aoff + rowOfs64, ag + (size_t)64 * K);
        cpa16(tb + STAGE_A + aoff, bg);
        if (BNT == 128)
            cpa16(tb + STAGE_A + aoff + rowOfs64, bg + (size_t)64 * K);
        cpa_commit();
    };

    float c[2][NFRAG][4];
#pragma unroll
    for (int i = 0; i < 2; ++i)
#pragma unroll
        for (int j = 0; j < NFRAG; ++j)
#pragma unroll
            for (int l = 0; l < 4; ++l) c[i][j][l] = 0.f;

    int KT = K / BKh;
    load_tile(0);
    load_tile(1);
    load_tile(2);

    for (int kt = 0; kt < KT; ++kt) {
        if (kt < KT - 2)       asm volatile("cp.async.wait_group 2;");
        else if (kt == KT - 2) asm volatile("cp.async.wait_group 1;");
        else                   asm volatile("cp.async.wait_group 0;");
        __syncthreads();                    // warps done with kt-1; tile kt visible

        if (kt + 3 < KT) load_tile(kt + 3); // overwrites buffer of kt-1: safe

        uint32_t aBase = s0 + (kt & (NST - 1)) * STAGEB;
        uint32_t bBase = aBase + STAGE_A;
#pragma unroll
        for (int ks = 0; ks < 2; ++ks) {
            uint32_t a[2][4];
#pragma unroll
            for (int mt = 0; mt < 2; ++mt) {
                int row = wm * 32 + mt * 16 + (lane & 15);
                int col = ks * 16 + (lane >> 4) * 8;
                ldsm4(a[mt][0], a[mt][1], a[mt][2], a[mt][3],
                      aBase + (row * ASTRIDE + col) * 2);
            }
            uint32_t b[NP][4];
#pragma unroll
            for (int p = 0; p < NP; ++p) {
                int nrow = wn * (BNT / 2) + p * 16 + (lane & 7) + ((lane >> 4) << 3);
                int col = ks * 16 + ((lane >> 3) & 1) * 8;
                ldsm4(b[p][0], b[p][1], b[p][2], b[p][3],
                      bBase + (nrow * ASTRIDE + col) * 2);
            }
#pragma unroll
            for (int mt = 0; mt < 2; ++mt)
#pragma unroll
                for (int nt = 0; nt < NFRAG; ++nt)
                    mma16816(c[mt][nt], a[mt][0], a[mt][1], a[mt][2], a[mt][3],
                             b[nt >> 1][(nt & 1) * 2], b[nt >> 1][(nt & 1) * 2 + 1]);
        }
    }

    // Epilogue
#pragma unroll
    for (int mt = 0; mt < 2; ++mt) {
#pragma unroll
        for (int nt = 0; nt < NFRAG; ++nt) {
            int r0 = bm + wm * 32 + mt * 16 + (lane >> 2);
            int col = bn + wn * (BNT / 2) + nt * 8 + (lane & 3) * 2;
            float sc0 = __ldg(&scales[col]);
            float sc1 = __ldg(&scales[col + 1]);
#pragma unroll
            for (int half = 0; half < 2; ++half) {
                int row = r0 + half * 8;
                float v0 = c[mt][nt][half * 2 + 0] * sc0;
                float v1 = c[mt][nt][half * 2 + 1] * sc1;
                if (EPI == 2) {
                    float g0 = 0.5f * v0 * (1.0f + erff(v0 * 0.70710678118654752440f));
                    float g1 = 0.5f * v1 * (1.0f + erff(v1 * 0.70710678118654752440f));
                    __half2 o = {__float2half_rn(g0), __float2half_rn(g1)};
                    *(__half2*)&Ch[(size_t)row * N + col] = o;
                } else if (EPI == 3) {
                    __half2 o = {__float2half_rn(v0), __float2half_rn(v1)};
                    *(__half2*)&Ch[(size_t)row * N + col] = o;
                } else if (EPI == 4) {
                    float2 r = *(const float2*)&Addf[(size_t)row * N + col];
                    __half2 o = {__float2half_rn(v0 + r.x), __float2half_rn(v1 + r.y)};
                    *(__half2*)&Ch[(size_t)row * N + col] = o;
                } else {  // EPI == 5
                    __half2 ah = *(const __half2*)&Addh[(size_t)row * N + col];
                    float2 r = __half22float2(ah);
                    float2 o = {v0 + r.x, v1 + r.y};
                    *(float2*)&Cf[(size_t)row * N + col] = o;
                }
            }
        }
    }
}

#define SMEM_128 (NST * (STAGE_A + 128 * ASTRIDE * 2))   // 81920
#define SMEM_64  (NST * (STAGE_A + 64 * ASTRIDE * 2))    // 61440

// ---------------------------------------------------------------------------
// Launch.  Quantize kernels run on a forked side-stream (event fork-join,
// graph-capturable) so they overlap rmsnorm1 + GEMM-3.
// ---------------------------------------------------------------------------
extern "C" void kernel_launch(void* const* d_in, const int* in_sizes, int n_in,
                              void* d_out, int out_size) {
    (void)in_sizes; (void)n_in; (void)out_size;
    const float* x    = (const float*)d_in[0];
    const float* n1w  = (const float*)d_in[1];
    const float* n2w  = (const float*)d_in[2];
    const float* w_in = (const float*)d_in[3];
    const float* w_o  = (const float*)d_in[4];
    const float* w_mi = (const float*)d_in[5];
    const float* w_mo = (const float*)d_in[6];
    const float* filt = (const float*)d_in[7];
    float* out = (float*)d_out;

    __half *p_wq_in, *p_wq_o, *p_wq_mi, *p_wq_mo, *p_h, *p_gated, *p_act, *p_x2;
    float *p_sc_in, *p_sc_o, *p_sc_mi, *p_sc_mo;
    cudaGetSymbolAddress((void**)&p_wq_in, g_wq_in);
    cudaGetSymbolAddress((void**)&p_wq_o,  g_wq_o);
    cudaGetSymbolAddress((void**)&p_wq_mi, g_wq_mi);
    cudaGetSymbolAddress((void**)&p_wq_mo, g_wq_mo);
    cudaGetSymbolAddress((void**)&p_sc_in, g_sc_in);
    cudaGetSymbolAddress((void**)&p_sc_o,  g_sc_o);
    cudaGetSymbolAddress((void**)&p_sc_mi, g_sc_mi);
    cudaGetSymbolAddress((void**)&p_sc_mo, g_sc_mo);
    cudaGetSymbolAddress((void**)&p_h,     g_h);
    cudaGetSymbolAddress((void**)&p_gated, g_gated);
    cudaGetSymbolAddress((void**)&p_act,   g_act);
    cudaGetSymbolAddress((void**)&p_x2,    g_x2);

    cudaFuncSetAttribute(mma_gemm<3,128>, cudaFuncAttributeMaxDynamicSharedMemorySize, SMEM_128);
    cudaFuncSetAttribute(mma_gemm<2,128>, cudaFuncAttributeMaxDynamicSharedMemorySize, SMEM_128);
    cudaFuncSetAttribute(mma_gemm<4,64>,  cudaFuncAttributeMaxDynamicSharedMemorySize, SMEM_64);
    cudaFuncSetAttribute(mma_gemm<5,64>,  cudaFuncAttributeMaxDynamicSharedMemorySize, SMEM_64);

    cudaStream_t s2;
    cudaEvent_t evFork, evQIn, evQRest;
    cudaStreamCreateWithFlags(&s2, cudaStreamNonBlocking);
    cudaEventCreateWithFlags(&evFork,  cudaEventDisableTiming);
    cudaEventCreateWithFlags(&evQIn,   cudaEventDisableTiming);
    cudaEventCreateWithFlags(&evQRest, cudaEventDisableTiming);

    // Fork: side stream joins the capture via event dependency.
    cudaEventRecord(evFork, 0);
    cudaStreamWaitEvent(s2, evFork, 0);

    // Side stream: all weight quantization (overlaps rmsnorm1 + GEMM-3).
    quantize_rows_kernel<<<MHn, 256, 0, s2>>>(w_in, p_wq_in, p_sc_in, Dn);
    cudaEventRecord(evQIn, s2);
    quantize_rows_kernel<<<Dn,  256, 0, s2>>>(w_o,  p_wq_o,  p_sc_o,  Dn);
    quantize_rows_kernel<<<MHn, 256, 0, s2>>>(w_mi, p_wq_mi, p_sc_mi, Dn);
    quantize_rows_kernel<<<Dn,  256, 0, s2>>>(w_mo, p_wq_mo, p_sc_mo, MHn);
    cudaEventRecord(evQRest, s2);

    // Main stream: 2) h = rmsnorm(x) -> fp16
    rmsnorm_kernel<<<Mtok, 256>>>(x, n1w, p_h);

    // Join #1: GEMM-3 needs wq_in.
    cudaStreamWaitEvent(0, evQIn, 0);

    // 3) qkv = h @ Wq_in^T -> fp16 (stored in g_act, dead after scan)
    mma_gemm<3,128><<<dim3(MHn / 128, Mtok / BM), 256, SMEM_128>>>(
        p_h, p_wq_in, p_sc_in, nullptr, nullptr, nullptr, p_act, Mtok, MHn, Dn);

    // 4) causal conv recurrence + SiLU gate -> fp16
    scan_gate_kernel<<<256, 256>>>(p_act, filt, p_gated);

    // Join #2: remaining GEMMs need wq_o / wq_mi / wq_mo.
    cudaStreamWaitEvent(0, evQRest, 0);

    // 5) x2 = fp16(x + gated @ Wq_o^T), BN=64, 3 CTAs/SM
    mma_gemm<4,64><<<dim3(Dn / 64, Mtok / BM), 256, SMEM_64>>>(
        p_gated, p_wq_o, p_sc_o, x, nullptr, nullptr, p_x2, Mtok, Dn, Dn);

    // 6) h2 = rmsnorm(x2) -> fp16 (fp16 input variant)
    rmsnorm_h_kernel<<<Mtok, 256>>>(p_x2, n2w, p_h);

    // 7) m = gelu(h2 @ Wq_mi^T) -> fp16 (overwrites g_act)
    mma_gemm<2,128><<<dim3(MHn / 128, Mtok / BM), 256, SMEM_128>>>(
        p_h, p_wq_mi, p_sc_mi, nullptr, nullptr, nullptr, p_act, Mtok, MHn, Dn);

    // 8) out = x2 + m @ Wq_mo^T (fp32 out, fp16 residual), BN=64, 3 CTAs/SM
    mma_gemm<5,64><<<dim3(Dn / 64, Mtok / BM), 256, SMEM_64>>>(
        p_act, p_wq_mo, p_sc_mo, nullptr, p_x2, out, nullptr, Mtok, Dn, MHn);

    // Host-side cleanup (not captured; graph retains the dependencies).
    cudaStreamDestroy(s2);
    cudaEventDestroy(evFork);
    cudaEventDestroy(evQIn);
    cudaEventDestroy(evQRest);
}

// round 17
// speedup vs baseline: 1.4616x; 1.0035x over previous
#include <cuda_runtime.h>
#include <cuda_fp16.h>
#include <math.h>
#include <stdint.h>

// Problem constants
#define Bsz   4
#define Tn    4096
#define Dn    1024
#define Hn    8
#define MHn   2048
#define Mtok  (Bsz * Tn)          // 16384 tokens
#define EPSv  1e-6f

// GEMM tile config (proven): 128(M) x BNT(N) CTA tile, BK=32/stage, NST=4,
// prefetch distance 3, wait_group 2, ONE sync per iteration.
#define BM 128
#define BKh 32
#define NST 4
#define ASTRIDE 40
#define STAGE_A  (BM * ASTRIDE * 2)             // 10240 B

// ---------------------------------------------------------------------------
// Device-global scratch (no cudaMalloc).
// ---------------------------------------------------------------------------
__device__ __half g_wq_in[(size_t)MHn * Dn];
__device__ __half g_wq_o [(size_t)Dn  * Dn];
__device__ __half g_wq_mi[(size_t)MHn * Dn];
__device__ __half g_wq_mo[(size_t)Dn  * MHn];
__device__ float g_sc_in[MHn];
__device__ float g_sc_o [Dn];
__device__ float g_sc_mi[MHn];
__device__ float g_sc_mo[Dn];
__device__ __half g_h    [(size_t)Mtok * Dn];
__device__ __half g_gated[(size_t)Mtok * Dn];
__device__ __half g_act  [(size_t)Mtok * MHn];
__device__ __half g_x2   [(size_t)Mtok * Dn];

// ---------------------------------------------------------------------------
// PTX helpers
// ---------------------------------------------------------------------------
__device__ __forceinline__ uint32_t smem_u32(const void* p) {
    return (uint32_t)__cvta_generic_to_shared(p);
}
__device__ __forceinline__ void cpa16(uint32_t s, const void* g) {
    asm volatile("cp.async.cg.shared.global [%0], [%1], 16;" :: "r"(s), "l"(g));
}
__device__ __forceinline__ void cpa_commit() {
    asm volatile("cp.async.commit_group;");
}
__device__ __forceinline__ void ldsm4(uint32_t& r0, uint32_t& r1, uint32_t& r2, uint32_t& r3,
                                      uint32_t addr) {
    asm volatile("ldmatrix.sync.aligned.m8n8.x4.shared.b16 {%0,%1,%2,%3}, [%4];"
                 : "=r"(r0), "=r"(r1), "=r"(r2), "=r"(r3) : "r"(addr));
}
__device__ __forceinline__ void mma16816(float* c, uint32_t a0, uint32_t a1, uint32_t a2,
                                         uint32_t a3, uint32_t b0, uint32_t b1) {
    asm volatile("mma.sync.aligned.m16n8k16.row.col.f32.f16.f16.f32 "
                 "{%0,%1,%2,%3}, {%4,%5,%6,%7}, {%8,%9}, {%0,%1,%2,%3};"
                 : "+f"(c[0]), "+f"(c[1]), "+f"(c[2]), "+f"(c[3])
                 : "r"(a0), "r"(a1), "r"(a2), "r"(a3), "r"(b0), "r"(b1));
}

// ---------------------------------------------------------------------------
// Quantize (register-resident single pass):
// wq[n,k] = fp16(round(w/scale)) exact integers; scales[n] = scale.
// ---------------------------------------------------------------------------
__global__ void quantize_rows_kernel(const float* __restrict__ w,
                                     __half* __restrict__ wq,
                                     float* __restrict__ scales, int C) {
    int row = blockIdx.x;
    int nv = C >> 10;
    const float4* wr = (const float4*)(w + (size_t)row * C);
    float4 v[2];
    float m = 0.f;
    for (int j = 0; j < nv; ++j) {
        v[j] = wr[j * 256 + threadIdx.x];
        m = fmaxf(m, fmaxf(fmaxf(fabsf(v[j].x), fabsf(v[j].y)),
                           fmaxf(fabsf(v[j].z), fabsf(v[j].w))));
    }
    __shared__ float sh[32];
    int lane = threadIdx.x & 31, wid = threadIdx.x >> 5;
#pragma unroll
    for (int o = 16; o; o >>= 1) m = fmaxf(m, __shfl_xor_sync(0xffffffffu, m, o));
    if (lane == 0) sh[wid] = m;
    __syncthreads();
    if (wid == 0) {
        float t = (lane < 8) ? sh[lane] : 0.f;
#pragma unroll
        for (int o = 4; o; o >>= 1) t = fmaxf(t, __shfl_xor_sync(0xffffffffu, t, o));
        if (lane == 0) sh[0] = t;
    }
    __syncthreads();
    float scale = fmaxf(sh[0] * (1.0f / 127.0f), 1e-8f);
    float inv = 1.0f / scale;
    if (threadIdx.x == 0) scales[row] = scale;
    for (int j = 0; j < nv; ++j) {
        __half2 h0 = {__float2half_rn(rintf(v[j].x * inv)), __float2half_rn(rintf(v[j].y * inv))};
        __half2 h1 = {__float2half_rn(rintf(v[j].z * inv)), __float2half_rn(rintf(v[j].w * inv))};
        uint2 o;
        o.x = *(uint32_t*)&h0;
        o.y = *(uint32_t*)&h1;
        *(uint2*)&wq[(size_t)row * C + (j * 256 + threadIdx.x) * 4] = o;
    }
}

// ---------------------------------------------------------------------------
// RMSNorm (fp32 input) -> fp16.  256 thr, 1 row/block, fully vectorized.
// ---------------------------------------------------------------------------
__global__ void rmsnorm_kernel(const float* __restrict__ x,
                               const float* __restrict__ w,
                               __half* __restrict__ out) {
    int row = blockIdx.x;
    const float4* xr = (const float4*)(x + (size_t)row * Dn);
    float4 v4 = xr[threadIdx.x];
    float ss = v4.x * v4.x + v4.y * v4.y + v4.z * v4.z + v4.w * v4.w;
    __shared__ float sh[32];
    int lane = threadIdx.x & 31, wid = threadIdx.x >> 5;
#pragma unroll
    for (int o = 16; o; o >>= 1) ss += __shfl_xor_sync(0xffffffffu, ss, o);
    if (lane == 0) sh[wid] = ss;
    __syncthreads();
    if (wid == 0) {
        float v = (lane < 8) ? sh[lane] : 0.f;
#pragma unroll
        for (int o = 4; o; o >>= 1) v += __shfl_xor_sync(0xffffffffu, v, o);
        if (lane == 0) sh[0] = v;
    }
    __syncthreads();
    float inv = rsqrtf(sh[0] * (1.0f / Dn) + EPSv);
    float4 w4 = ((const float4*)w)[threadIdx.x];
    __half2 o0 = {__float2half_rn(v4.x * inv * w4.x), __float2half_rn(v4.y * inv * w4.y)};
    __half2 o1 = {__float2half_rn(v4.z * inv * w4.z), __float2half_rn(v4.w * inv * w4.w)};
    uint2 o;
    o.x = *(uint32_t*)&o0;
    o.y = *(uint32_t*)&o1;
    *(uint2*)&out[(size_t)row * Dn + threadIdx.x * 4] = o;
}

// ---------------------------------------------------------------------------
// RMSNorm (fp16 input) -> fp16.  For the fp16 residual stream x2.
// ---------------------------------------------------------------------------
__global__ void rmsnorm_h_kernel(const __half* __restrict__ x,
                                 const float* __restrict__ w,
                                 __half* __restrict__ out) {
    int row = blockIdx.x;
    uint2 raw = *(const uint2*)&x[(size_t)row * Dn + threadIdx.x * 4];
    __half2 x0 = *(__half2*)&raw.x;
    __half2 x1 = *(__half2*)&raw.y;
    float2 f0 = __half22float2(x0);
    float2 f1 = __half22float2(x1);
    float ss = f0.x * f0.x + f0.y * f0.y + f1.x * f1.x + f1.y * f1.y;
    __shared__ float sh[32];
    int lane = threadIdx.x & 31, wid = threadIdx.x >> 5;
#pragma unroll
    for (int o = 16; o; o >>= 1) ss += __shfl_xor_sync(0xffffffffu, ss, o);
    if (lane == 0) sh[wid] = ss;
    __syncthreads();
    if (wid == 0) {
        float v = (lane < 8) ? sh[lane] : 0.f;
#pragma unroll
        for (int o = 4; o; o >>= 1) v += __shfl_xor_sync(0xffffffffu, v, o);
        if (lane == 0) sh[0] = v;
    }
    __syncthreads();
    float inv = rsqrtf(sh[0] * (1.0f / Dn) + EPSv);
    float4 w4 = ((const float4*)w)[threadIdx.x];
    __half2 o0 = {__float2half_rn(f0.x * inv * w4.x), __float2half_rn(f0.y * inv * w4.y)};
    __half2 o1 = {__float2half_rn(f1.x * inv * w4.z), __float2half_rn(f1.y * inv * w4.w)};
    uint2 o;
    o.x = *(uint32_t*)&o0;
    o.y = *(uint32_t*)&o1;
    *(uint2*)&out[(size_t)row * Dn + threadIdx.x * 4] = o;
}

// ---------------------------------------------------------------------------
// Causal exp-filter conv (linear recurrence) + SiLU gate, fp16 qkv.
// 32 chunks of 128 steps (warmup 128: alpha^128 = e^-12.8 ~ 3e-6, negligible).
// 512 blocks x 128 threads (3.46 blocks/SM -> balanced); half2 channel pairs.
// ---------------------------------------------------------------------------
#define SCH 128
__global__ void scan_gate_kernel(const __half* __restrict__ qkv,
                                 const float* __restrict__ filt,
                                 __half* __restrict__ gated) {
    int tid = threadIdx.x;                    // 0..127
    int chunk = blockIdx.x & 31;
    int b = (blockIdx.x >> 5) & 3;
    int cg = blockIdx.x >> 7;                 // 0..3
    int c = cg * 256 + tid * 2;               // even channel; pair same head
    int h = c >> 7;
    float f0 = filt[h];
    float alpha = filt[Hn + h] / f0;
    const __half2* sb = (const __half2*)(qkv + (size_t)b * Tn * MHn + c);
    const __half2* gb = (const __half2*)(qkv + (size_t)b * Tn * MHn + Dn + c);
    __half2* ob = (__half2*)(gated + (size_t)b * Tn * Dn + c);
    const int qs = MHn / 2, os = Dn / 2;
    float y0 = 0.f, y1 = 0.f;
    int t0 = chunk * SCH;
    if (chunk) {
#pragma unroll 4
        for (int t = t0 - SCH; t < t0; ++t) {
            float2 s = __half22float2(__ldg(&sb[(size_t)t * qs]));
            y0 = fmaf(alpha, y0, s.x);
            y1 = fmaf(alpha, y1, s.y);
        }
    }
#pragma unroll 2
    for (int t = t0; t < t0 + SCH; ++t) {
        float2 s = __half22float2(__ldg(&sb[(size_t)t * qs]));
        float2 g = __half22float2(__ldg(&gb[(size_t)t * qs]));
        y0 = fmaf(alpha, y0, s.x);
        y1 = fmaf(alpha, y1, s.y);
        float v0 = (f0 * y0) * (g.x / (1.0f + __expf(-g.x)));
        float v1 = (f0 * y1) * (g.y / (1.0f + __expf(-g.y)));
        ob[(size_t)t * os] = __floats2half2_rn(v0, v1);
    }
}

// ---------------------------------------------------------------------------
// fp16 tensor-core GEMM: v[m,n] = (sum_k A[m,k]*W[n,k]) * scales[n]
//   EPI 2: Ch = fp16(gelu(v))       EPI 3: Ch = fp16(v)
//   EPI 4: Ch = fp16(v + Addf)      EPI 5: Cf = v + Addh (fp32 out)
// 128 x BNT tile, 8 warps (4m x 2n; warp tile 32 x BNT/2), BK=32, NST=4,
// prefetch 3, wait_group 2, ONE __syncthreads per iteration.
// BNT=128 -> 2 CTAs/SM;  BNT=64 -> 3 CTAs/SM.
// ---------------------------------------------------------------------------
template <int EPI, int BNT>
__global__ __launch_bounds__(256, (BNT == 64) ? 3 : 2)
void mma_gemm(const __half* __restrict__ A, const __half* __restrict__ W,
              const float* __restrict__ scales,
              const float* __restrict__ Addf, const __half* __restrict__ Addh,
              float* __restrict__ Cf, __half* __restrict__ Ch,
              int M, int N, int K) {
    constexpr int STAGE_B = BNT * ASTRIDE * 2;
    constexpr int STAGEB  = STAGE_A + STAGE_B;
    constexpr int NFRAG   = BNT / 16;
    constexpr int NP      = BNT / 32;

    extern __shared__ char smem[];
    uint32_t s0 = smem_u32(smem);

    int tid = threadIdx.x;
    int bm = blockIdx.y * BM;
    int bn = blockIdx.x * BNT;
    int lane = tid & 31, wid = tid >> 5;
    int wm = wid >> 1, wn = wid & 1;

    int lr = tid >> 2;
    int lc = tid & 3;

    const __half* Ab = A + (size_t)(bm + lr) * K + lc * 8;
    const __half* Bb = W + (size_t)(bn + lr) * K + lc * 8;
    uint32_t aoff = (uint32_t)(lr * ASTRIDE + lc * 8) * 2;
    const uint32_t rowOfs64 = 64 * ASTRIDE * 2;

    auto load_tile = [&](int kt) {
        uint32_t tb = s0 + (kt & (NST - 1)) * STAGEB;
        const __half* ag = Ab + (size_t)kt * BKh;
        const __half* bg = Bb + (size_t)kt * BKh;
        cpa16(tb + aoff, ag);
        cpa16(tb + aoff + rowOfs64, ag + (size_t)64 * K);
        cpa16(tb + STAGE_A + aoff, bg);
        if (BNT == 128)
            cpa16(tb + STAGE_A + aoff + rowOfs64, bg + (size_t)64 * K);
        cpa_commit();
    };

    float c[2][NFRAG][4];
#pragma unroll
    for (int i = 0; i < 2; ++i)
#pragma unroll
        for (int j = 0; j < NFRAG; ++j)
#pragma unroll
            for (int l = 0; l < 4; ++l) c[i][j][l] = 0.f;

    int KT = K / BKh;
    load_tile(0);
    load_tile(1);
    load_tile(2);

    for (int kt = 0; kt < KT; ++kt) {
        if (kt < KT - 2)       asm volatile("cp.async.wait_group 2;");
        else if (kt == KT - 2) asm volatile("cp.async.wait_group 1;");
        else                   asm volatile("cp.async.wait_group 0;");
        __syncthreads();                    // warps done with kt-1; tile kt visible

        if (kt + 3 < KT) load_tile(kt + 3); // overwrites buffer of kt-1: safe

        uint32_t aBase = s0 + (kt & (NST - 1)) * STAGEB;
        uint32_t bBase = aBase + STAGE_A;
#pragma unroll
        for (int ks = 0; ks < 2; ++ks) {
            uint32_t a[2][4];
#pragma unroll
            for (int mt = 0; mt < 2; ++mt) {
                int row = wm * 32 + mt * 16 + (lane & 15);
                int col = ks * 16 + (lane >> 4) * 8;
                ldsm4(a[mt][0], a[mt][1], a[mt][2], a[mt][3],
                      aBase + (row * ASTRIDE + col) * 2);
            }
            uint32_t b[NP][4];
#pragma unroll
            for (int p = 0; p < NP; ++p) {
                int nrow = wn * (BNT / 2) + p * 16 + (lane & 7) + ((lane >> 4) << 3);
                int col = ks * 16 + ((lane >> 3) & 1) * 8;
                ldsm4(b[p][0], b[p][1], b[p][2], b[p][3],
                      bBase + (nrow * ASTRIDE + col) * 2);
            }
#pragma unroll
            for (int mt = 0; mt < 2; ++mt)
#pragma unroll
                for (int nt = 0; nt < NFRAG; ++nt)
                    mma16816(c[mt][nt], a[mt][0], a[mt][1], a[mt][2], a[mt][3],
                             b[nt >> 1][(nt & 1) * 2], b[nt >> 1][(nt & 1) * 2 + 1]);
        }
    }

    // Epilogue
#pragma unroll
    for (int mt = 0; mt < 2; ++mt) {
#pragma unroll
        for (int nt = 0; nt < NFRAG; ++nt) {
            int r0 = bm + wm * 32 + mt * 16 + (lane >> 2);
            int col = bn + wn * (BNT / 2) + nt * 8 + (lane & 3) * 2;
            float sc0 = __ldg(&scales[col]);
            float sc1 = __ldg(&scales[col + 1]);
#pragma unroll
            for (int half = 0; half < 2; ++half) {
                int row = r0 + half * 8;
                float v0 = c[mt][nt][half * 2 + 0] * sc0;
                float v1 = c[mt][nt][half * 2 + 1] * sc1;
                if (EPI == 2) {
                    float g0 = 0.5f * v0 * (1.0f + erff(v0 * 0.70710678118654752440f));
                    float g1 = 0.5f * v1 * (1.0f + erff(v1 * 0.70710678118654752440f));
                    __half2 o = {__float2half_rn(g0), __float2half_rn(g1)};
                    *(__half2*)&Ch[(size_t)row * N + col] = o;
                } else if (EPI == 3) {
                    __half2 o = {__float2half_rn(v0), __float2half_rn(v1)};
                    *(__half2*)&Ch[(size_t)row * N + col] = o;
                } else if (EPI == 4) {
                    float2 r = *(const float2*)&Addf[(size_t)row * N + col];
                    __half2 o = {__float2half_rn(v0 + r.x), __float2half_rn(v1 + r.y)};
                    *(__half2*)&Ch[(size_t)row * N + col] = o;
                } else {  // EPI == 5
                    __half2 ah = *(const __half2*)&Addh[(size_t)row * N + col];
                    float2 r = __half22float2(ah);
                    float2 o = {v0 + r.x, v1 + r.y};
                    *(float2*)&Cf[(size_t)row * N + col] = o;
                }
            }
        }
    }
}

#define SMEM_128 (NST * (STAGE_A + 128 * ASTRIDE * 2))   // 81920
#define SMEM_64  (NST * (STAGE_A + 64 * ASTRIDE * 2))    // 61440

// ---------------------------------------------------------------------------
// Launch.  Quantize kernels run on a forked side-stream (event fork-join,
// graph-capturable, no cross-kernel spins) so they overlap rmsnorm1 + GEMM-3.
// ---------------------------------------------------------------------------
extern "C" void kernel_launch(void* const* d_in, const int* in_sizes, int n_in,
                              void* d_out, int out_size) {
    (void)in_sizes; (void)n_in; (void)out_size;
    const float* x    = (const float*)d_in[0];
    const float* n1w  = (const float*)d_in[1];
    const float* n2w  = (const float*)d_in[2];
    const float* w_in = (const float*)d_in[3];
    const float* w_o  = (const float*)d_in[4];
    const float* w_mi = (const float*)d_in[5];
    const float* w_mo = (const float*)d_in[6];
    const float* filt = (const float*)d_in[7];
    float* out = (float*)d_out;

    __half *p_wq_in, *p_wq_o, *p_wq_mi, *p_wq_mo, *p_h, *p_gated, *p_act, *p_x2;
    float *p_sc_in, *p_sc_o, *p_sc_mi, *p_sc_mo;
    cudaGetSymbolAddress((void**)&p_wq_in, g_wq_in);
    cudaGetSymbolAddress((void**)&p_wq_o,  g_wq_o);
    cudaGetSymbolAddress((void**)&p_wq_mi, g_wq_mi);
    cudaGetSymbolAddress((void**)&p_wq_mo, g_wq_mo);
    cudaGetSymbolAddress((void**)&p_sc_in, g_sc_in);
    cudaGetSymbolAddress((void**)&p_sc_o,  g_sc_o);
    cudaGetSymbolAddress((void**)&p_sc_mi, g_sc_mi);
    cudaGetSymbolAddress((void**)&p_sc_mo, g_sc_mo);
    cudaGetSymbolAddress((void**)&p_h,     g_h);
    cudaGetSymbolAddress((void**)&p_gated, g_gated);
    cudaGetSymbolAddress((void**)&p_act,   g_act);
    cudaGetSymbolAddress((void**)&p_x2,    g_x2);

    cudaFuncSetAttribute(mma_gemm<3,128>, cudaFuncAttributeMaxDynamicSharedMemorySize, SMEM_128);
    cudaFuncSetAttribute(mma_gemm<2,128>, cudaFuncAttributeMaxDynamicSharedMemorySize, SMEM_128);
    cudaFuncSetAttribute(mma_gemm<4,64>,  cudaFuncAttributeMaxDynamicSharedMemorySize, SMEM_64);
    cudaFuncSetAttribute(mma_gemm<5,64>,  cudaFuncAttributeMaxDynamicSharedMemorySize, SMEM_64);

    cudaStream_t s2;
    cudaEvent_t evFork, evQIn, evQRest;
    cudaStreamCreateWithFlags(&s2, cudaStreamNonBlocking);
    cudaEventCreateWithFlags(&evFork,  cudaEventDisableTiming);
    cudaEventCreateWithFlags(&evQIn,   cudaEventDisableTiming);
    cudaEventCreateWithFlags(&evQRest, cudaEventDisableTiming);

    // Fork: side stream joins the capture via event dependency.
    cudaEventRecord(evFork, 0);
    cudaStreamWaitEvent(s2, evFork, 0);

    // Side stream: all weight quantization (overlaps rmsnorm1 + GEMM-3).
    quantize_rows_kernel<<<MHn, 256, 0, s2>>>(w_in, p_wq_in, p_sc_in, Dn);
    cudaEventRecord(evQIn, s2);
    quantize_rows_kernel<<<Dn,  256, 0, s2>>>(w_o,  p_wq_o,  p_sc_o,  Dn);
    quantize_rows_kernel<<<MHn, 256, 0, s2>>>(w_mi, p_wq_mi, p_sc_mi, Dn);
    quantize_rows_kernel<<<Dn,  256, 0, s2>>>(w_mo, p_wq_mo, p_sc_mo, MHn);
    cudaEventRecord(evQRest, s2);

    // Main stream: 2) h = rmsnorm(x) -> fp16
    rmsnorm_kernel<<<Mtok, 256>>>(x, n1w, p_h);

    // Join #1: GEMM-3 needs wq_in.
    cudaStreamWaitEvent(0, evQIn, 0);

    // 3) qkv = h @ Wq_in^T -> fp16 (stored in g_act, dead after scan)
    mma_gemm<3,128><<<dim3(MHn / 128, Mtok / BM), 256, SMEM_128>>>(
        p_h, p_wq_in, p_sc_in, nullptr, nullptr, nullptr, p_act, Mtok, MHn, Dn);

    // 4) causal conv recurrence + SiLU gate -> fp16 (512 balanced blocks)
    scan_gate_kernel<<<512, 128>>>(p_act, filt, p_gated);

    // Join #2: remaining GEMMs need wq_o / wq_mi / wq_mo.
    cudaStreamWaitEvent(0, evQRest, 0);

    // 5) x2 = fp16(x + gated @ Wq_o^T), BN=64, 3 CTAs/SM
    mma_gemm<4,64><<<dim3(Dn / 64, Mtok / BM), 256, SMEM_64>>>(
        p_gated, p_wq_o, p_sc_o, x, nullptr, nullptr, p_x2, Mtok, Dn, Dn);

    // 6) h2 = rmsnorm(x2) -> fp16 (fp16 input variant)
    rmsnorm_h_kernel<<<Mtok, 256>>>(p_x2, n2w, p_h);

    // 7) m = gelu(h2 @ Wq_mi^T) -> fp16 (overwrites g_act)
    mma_gemm<2,128><<<dim3(MHn / 128, Mtok / BM), 256, SMEM_128>>>(
        p_h, p_wq_mi, p_sc_mi, nullptr, nullptr, nullptr, p_act, Mtok, MHn, Dn);

    // 8) out = x2 + m @ Wq_mo^T (fp32 out, fp16 residual), BN=64, 3 CTAs/SM
    mma_gemm<5,64><<<dim3(Dn / 64, Mtok / BM), 256, SMEM_64>>>(
        p_act, p_wq_mo, p_sc_mo, nullptr, p_x2, out, nullptr, Mtok, Dn, MHn);

    // Host-side cleanup (not captured; graph retains the dependencies).
    cudaStreamDestroy(s2);
    cudaEventDestroy(evFork);
    cudaEventDestroy(evQIn);
    cudaEventDestroy(evQRest);
}